// round 10
// baseline (speedup 1.0000x reference)
#include <cuda_runtime.h>
#include <cstdint>

#define BATCH 128
#define SEQ   512
#define IDIM  256
#define HDIM  512
#define G4    2048

// ---- persistent scan tiling ----
#define NBLK  128     // 4 batch-tiles x 32 j-tiles
#define NTHR  512     // 16 warps: warp = ks(4) x jg(4); lane = batch
#define BJ    16
#define BB    32
#define SROW  132     // staging row floats (128 + 4) -> 528B, 16B-aligned rows
#define COFF  4224    // c offset inside a staging buffer (32*132)
#define BUFS  8448    // staging buffer stride (h+c)
#define WTOT  40960   // weight floats: 80 rows x 512
#define PSTR_J 15     // part: 5 gates x 3 publishers
#define PSTR_B 241    // part: 16 j x 15 + 1 pad (odd bank stride, conflict-free)
#define SMEM_SCAN ((WTOT + 2*BUFS) * 4)   // 231424 B (<= 227KB limit)

// ---- device-global scratch (no cudaMalloc allowed) ----
__device__ float g_h[2][BATCH][HDIM];
__device__ float g_c[2][BATCH][HDIM];
__device__ float g_u[SEQ][BATCH][G4];
__device__ unsigned g_bar[2];

__device__ __forceinline__ unsigned long long fma2(unsigned long long a,
                                                   unsigned long long b,
                                                   unsigned long long c) {
    unsigned long long d;
    asm("fma.rn.f32x2 %0, %1, %2, %3;" : "=l"(d) : "l"(a), "l"(b), "l"(c));
    return d;
}
__device__ __forceinline__ float red2(unsigned long long a) {
    return __uint_as_float((unsigned)a) + __uint_as_float((unsigned)(a >> 32));
}
__device__ __forceinline__ float sigm(float x) {
    return 1.0f / (1.0f + __expf(-x));
}
__device__ __forceinline__ float tanhfast(float x) {
    float y;
    asm("tanh.approx.f32 %0, %1;" : "=f"(y) : "f"(x));
    return y;
}

// =====================================================================
// Kernel 1: u_pre[s][b][g] (unchanged from R5 best)
// =====================================================================
__global__ void __launch_bounds__(128)
u_gemm_kernel(const float* __restrict__ X, const float* __restrict__ Uw,
              const float* __restrict__ Ub) {
    __shared__ float As[64][36];
    __shared__ float Bs[64][36];
    const int g0 = blockIdx.x * 64;
    const int r0 = blockIdx.y * 64;
    const int tid = threadIdx.x;
    const int tx = tid & 7;
    const int ty = tid >> 3;

    unsigned long long acc[4][8] = {};

    for (int k0 = 0; k0 < IDIM; k0 += 32) {
#pragma unroll
        for (int q = 0; q < 4; ++q) {
            int idx = tid + q * 128;
            int row = idx >> 3;
            int c4  = (idx & 7) << 2;
            *(float4*)&As[row][c4] = *(const float4*)&X[(size_t)(r0 + row) * IDIM + k0 + c4];
            *(float4*)&Bs[row][c4] = *(const float4*)&Uw[(size_t)(g0 + row) * IDIM + k0 + c4];
        }
        __syncthreads();
#pragma unroll
        for (int k = 0; k < 32; k += 2) {
            unsigned long long a[4], b[8];
#pragma unroll
            for (int mi = 0; mi < 4; ++mi) a[mi] = *(const unsigned long long*)&As[ty * 4 + mi][k];
#pragma unroll
            for (int ni = 0; ni < 8; ++ni) b[ni] = *(const unsigned long long*)&Bs[tx + ni * 8][k];
#pragma unroll
            for (int mi = 0; mi < 4; ++mi)
#pragma unroll
                for (int ni = 0; ni < 8; ++ni)
                    acc[mi][ni] = fma2(a[mi], b[ni], acc[mi][ni]);
        }
        __syncthreads();
    }
#pragma unroll
    for (int mi = 0; mi < 4; ++mi) {
        int r = r0 + ty * 4 + mi;
        int b = r >> 9;
        int s = r & 511;
        float* orow = &g_u[s][b][0];
#pragma unroll
        for (int ni = 0; ni < 8; ++ni) {
            int g = g0 + tx + ni * 8;
            orow[g] = red2(acc[mi][ni]) + Ub[g];
        }
    }
}

// =====================================================================
// Kernel 2: persistent scan. 128 CTAs x 512 threads.
// lane = batch (32 per warp); warp = ks(4 k-slices) x jg(4 j-groups).
// Thread = 1b x 4j x 128k -> 20 packed accums. Weight LDS warp-uniform
// (pure broadcast, unpadded 160KB); state LDS 1 row/lane (4-bank row
// stride -> phase-conflict-free). Double-buffered k-quarter staging
// (1 sync/quarter, LDG prefetch overlapped). k-partials combined via
// conflict-free SMEM exchange; ks=0 warps run the epilogue with float4
// u/c loads and tanh.approx.
// =====================================================================
__global__ void __launch_bounds__(NTHR, 1)
timelstm_scan_kernel(const float* __restrict__ Wall, const float* __restrict__ Wallb,
                     const float* __restrict__ Wd,   const float* __restrict__ Wdb,
                     const float* __restrict__ ts,   float* __restrict__ out) {
    extern __shared__ float sm[];
    float* sWg = sm;                         // 80 rows x 512 (gates then decay)
    float* stg = sm + WTOT;                  // 2 x (h[32][132] + c[32][132])
    float* part = stg;                       // reduction region (reuses staging)

    const int tid  = threadIdx.x;
    const int lane = tid & 31;
    const int warp = tid >> 5;
    const int ks   = warp >> 2;              // 0..3 k-slice (finishers: ks==0)
    const int jg   = warp & 3;               // 0..3 j-group

    const int jt = blockIdx.x >> 2;
    const int bt = blockIdx.x & 3;
    const int j0 = jt * BJ;
    const int b0 = bt * BB;
    const int b  = b0 + lane;
    const int jbase = j0 + jg * 4;

    // ---- preload weights (once): rows 0..63 gates (g*16+jl), 64..79 decay ----
    for (int idx = tid; idx < 80 * 128; idx += NTHR) {
        int row = idx >> 7;
        int c4  = (idx & 127) << 2;
        const float* srcp = (row < 64)
            ? &Wall[(size_t)((row >> 4) * HDIM + j0 + (row & 15)) * HDIM + c4]
            : &Wd[(size_t)(j0 + row - 64) * HDIM + c4];
        *(float4*)&sWg[row * HDIM + c4] = *(const float4*)srcp;
    }
    // biases for finisher outputs (4 j each)
    float bF[4], bI[4], bO[4], bCt[4], bD[4];
#pragma unroll
    for (int ji = 0; ji < 4; ++ji) {
        int jj = jbase + ji;
        bF[ji]  = Wallb[0 * HDIM + jj];
        bI[ji]  = Wallb[1 * HDIM + jj];
        bO[ji]  = Wallb[2 * HDIM + jj];
        bCt[ji] = Wallb[3 * HDIM + jj];
        bD[ji]  = Wdb[jj];
    }
    __syncthreads();

    // weight thread base: +ji*512, +g*8192 (g=4 -> decay rows), +kcol
    const float* wbase = sWg + (jg * 4) * HDIM;
    // state LDS base: own batch row, own k-slice
    const float* hb = stg + lane * SROW + ks * 32;

    // staging writer mapping: 2 float4 of h + 2 of c per thread per quarter
    const int sr0 = tid >> 5;                 // rows 0..15
    const int scl = (tid & 31) << 2;          // cols 0..124
    float* sd0 = stg + sr0 * SROW + scl;
    float* sd1 = stg + (sr0 + 16) * SROW + scl;

    for (int s = 0; s < SEQ; ++s) {
        const int cur = s & 1, nxt = cur ^ 1;
        const float* hg = &g_h[cur][b0][0];
        const float* cg = &g_c[cur][b0][0];

        unsigned long long acc[4][5];
#pragma unroll
        for (int ji = 0; ji < 4; ++ji)
#pragma unroll
            for (int g = 0; g < 5; ++g) acc[ji][g] = 0ull;

        // ---- prologue: stage quarter 0 into buf0 ----
        {
            float4 h0 = __ldcg((const float4*)(hg + (size_t)sr0 * HDIM + scl));
            float4 h1 = __ldcg((const float4*)(hg + (size_t)(sr0 + 16) * HDIM + scl));
            float4 c0 = __ldcg((const float4*)(cg + (size_t)sr0 * HDIM + scl));
            float4 c1 = __ldcg((const float4*)(cg + (size_t)(sr0 + 16) * HDIM + scl));
            *(float4*)sd0 = h0; *(float4*)sd1 = h1;
            *(float4*)(sd0 + COFF) = c0; *(float4*)(sd1 + COFF) = c1;
        }
        __syncthreads();

#pragma unroll 1
        for (int q = 0; q < 4; ++q) {
            const int buf = q & 1;
            float4 nh0, nh1, nc0, nc1;
            if (q < 3) {   // prefetch next quarter while computing
                int ko = (q + 1) * 128 + scl;
                nh0 = __ldcg((const float4*)(hg + (size_t)sr0 * HDIM + ko));
                nh1 = __ldcg((const float4*)(hg + (size_t)(sr0 + 16) * HDIM + ko));
                nc0 = __ldcg((const float4*)(cg + (size_t)sr0 * HDIM + ko));
                nc1 = __ldcg((const float4*)(cg + (size_t)(sr0 + 16) * HDIM + ko));
            }

            const float* hp = hb + buf * BUFS;
            const float* wq = wbase + q * 128 + ks * 32;
#pragma unroll
            for (int it = 0; it < 8; ++it) {
                const int kk = it * 4;
                ulonglong2 hv = *(const ulonglong2*)(hp + kk);
                ulonglong2 cv = *(const ulonglong2*)(hp + COFF + kk);
#pragma unroll
                for (int ji = 0; ji < 4; ++ji) {
                    const float* wj = wq + ji * HDIM + kk;
                    ulonglong2 vF = *(const ulonglong2*)(wj + 0 * 8192);
                    acc[ji][0] = fma2(hv.x, vF.x, acc[ji][0]);
                    acc[ji][0] = fma2(hv.y, vF.y, acc[ji][0]);
                    ulonglong2 vI = *(const ulonglong2*)(wj + 1 * 8192);
                    acc[ji][1] = fma2(hv.x, vI.x, acc[ji][1]);
                    acc[ji][1] = fma2(hv.y, vI.y, acc[ji][1]);
                    ulonglong2 vO = *(const ulonglong2*)(wj + 2 * 8192);
                    acc[ji][2] = fma2(hv.x, vO.x, acc[ji][2]);
                    acc[ji][2] = fma2(hv.y, vO.y, acc[ji][2]);
                    ulonglong2 vC = *(const ulonglong2*)(wj + 3 * 8192);
                    acc[ji][3] = fma2(hv.x, vC.x, acc[ji][3]);
                    acc[ji][3] = fma2(hv.y, vC.y, acc[ji][3]);
                    ulonglong2 vD = *(const ulonglong2*)(wj + 4 * 8192);
                    acc[ji][4] = fma2(cv.x, vD.x, acc[ji][4]);
                    acc[ji][4] = fma2(cv.y, vD.y, acc[ji][4]);
                }
            }

            if (q < 3) {   // store next quarter into the other buffer
                float* nd0 = sd0 + (buf ^ 1) * BUFS;
                float* nd1 = sd1 + (buf ^ 1) * BUFS;
                *(float4*)nd0 = nh0; *(float4*)nd1 = nh1;
                *(float4*)(nd0 + COFF) = nc0; *(float4*)(nd1 + COFF) = nc1;
            }
            __syncthreads();
        }

        // ---- collapse packed halves ----
        float r[4][5];
#pragma unroll
        for (int ji = 0; ji < 4; ++ji)
#pragma unroll
            for (int g = 0; g < 5; ++g) r[ji][g] = red2(acc[ji][g]);

        // ---- k-partial exchange: ks=1..3 publish; ks=0 loads epilogue data ----
        float4 uF, uI, uO, uCt, cold4;
        float tv = 0.0f;
        if (ks) {
            float* pp = part + lane * PSTR_B + (ks - 1);
#pragma unroll
            for (int ji = 0; ji < 4; ++ji)
#pragma unroll
                for (int g = 0; g < 5; ++g)
                    pp[(jg * 4 + ji) * PSTR_J + g * 3] = r[ji][g];
        } else {
            const float* ub = &g_u[s][b][0];
            uF   = __ldcg((const float4*)(ub + 0 * HDIM + jbase));
            uI   = __ldcg((const float4*)(ub + 1 * HDIM + jbase));
            uO   = __ldcg((const float4*)(ub + 2 * HDIM + jbase));
            uCt  = __ldcg((const float4*)(ub + 3 * HDIM + jbase));
            cold4 = __ldcg((const float4*)&g_c[cur][b][jbase]);
            tv   = ts[(size_t)b * SEQ + s];
        }
        __syncthreads();

        // ---- epilogue on ks==0 warps: 1b x 4j per thread ----
        if (ks == 0) {
            const float* pp = part + lane * PSTR_B;
            float cn[4], hn[4];
            const float uf_[4]  = {uF.x, uF.y, uF.z, uF.w};
            const float ui_[4]  = {uI.x, uI.y, uI.z, uI.w};
            const float uo_[4]  = {uO.x, uO.y, uO.z, uO.w};
            const float uc_[4]  = {uCt.x, uCt.y, uCt.z, uCt.w};
            const float co_[4]  = {cold4.x, cold4.y, cold4.z, cold4.w};
#pragma unroll
            for (int ji = 0; ji < 4; ++ji) {
                const float* pj = pp + (jg * 4 + ji) * PSTR_J;
                float F  = r[ji][0] + pj[0]  + pj[1]  + pj[2]  + bF[ji]  + uf_[ji];
                float I_ = r[ji][1] + pj[3]  + pj[4]  + pj[5]  + bI[ji]  + ui_[ji];
                float O_ = r[ji][2] + pj[6]  + pj[7]  + pj[8]  + bO[ji]  + uo_[ji];
                float Ct = r[ji][3] + pj[9]  + pj[10] + pj[11] + bCt[ji] + uc_[ji];
                float D  = r[ji][4] + pj[12] + pj[13] + pj[14] + bD[ji];
                float f   = sigm(F);
                float ii  = sigm(I_);
                float oo  = sigm(O_);
                float ct  = sigm(Ct);
                float cs1 = tanhfast(D);
                float cadj = co_[ji] + cs1 * (tv - 1.0f);   // c - cs1 + cs1*t
                float cnew = f * cadj + ii * ct;
                cn[ji] = cnew;
                hn[ji] = oo * tanhfast(cnew);
            }
            *(float4*)&g_c[nxt][b][jbase] = make_float4(cn[0], cn[1], cn[2], cn[3]);
            *(float4*)&g_h[nxt][b][jbase] = make_float4(hn[0], hn[1], hn[2], hn[3]);
            *(float4*)&out[((size_t)b * SEQ + s) * HDIM + jbase] =
                make_float4(hn[0], hn[1], hn[2], hn[3]);
        }

        // ---- grid barrier ----
        __syncthreads();
        if (tid == 0) {
            volatile unsigned* vgen = &g_bar[1];
            unsigned gen = *vgen;
            __threadfence();
            if (atomicAdd(&g_bar[0], 1u) == NBLK - 1u) {
                g_bar[0] = 0u;
                __threadfence();
                *vgen = gen + 1u;
            } else {
                while (*vgen == gen) { }
            }
            __threadfence();
        }
        __syncthreads();
    }
}

// =====================================================================
extern "C" void kernel_launch(void* const* d_in, const int* in_sizes, int n_in,
                              void* d_out, int out_size) {
    const float* X     = (const float*)d_in[0];
    const float* T     = (const float*)d_in[1];
    const float* Wall  = (const float*)d_in[2];
    const float* Wallb = (const float*)d_in[3];
    const float* Uw    = (const float*)d_in[4];
    const float* Ubb   = (const float*)d_in[5];
    const float* Wd    = (const float*)d_in[6];
    const float* Wdb   = (const float*)d_in[7];
    float* out = (float*)d_out;

    void *hp, *cp, *bp;
    cudaGetSymbolAddress(&hp, g_h);
    cudaGetSymbolAddress(&cp, g_c);
    cudaGetSymbolAddress(&bp, g_bar);
    cudaMemsetAsync(hp, 0, sizeof(float) * 2 * BATCH * HDIM, 0);
    cudaMemsetAsync(cp, 0, sizeof(float) * 2 * BATCH * HDIM, 0);
    cudaMemsetAsync(bp, 0, sizeof(unsigned) * 2, 0);

    dim3 ugrid(G4 / 64, (BATCH * SEQ) / 64);
    u_gemm_kernel<<<ugrid, 128>>>(X, Uw, Ubb);

    cudaFuncSetAttribute(timelstm_scan_kernel,
                         cudaFuncAttributeMaxDynamicSharedMemorySize, SMEM_SCAN);
    timelstm_scan_kernel<<<NBLK, NTHR, SMEM_SCAN>>>(Wall, Wallb, Wd, Wdb, T, out);
}

// round 12
// speedup vs baseline: 1.3522x; 1.3522x over previous
#include <cuda_runtime.h>
#include <cuda_bf16.h>
#include <cstdint>

#define BATCH 128
#define SEQ   512
#define IDIM  256
#define HDIM  512
#define G4    2048

// ---- scan geometry: 128 CTAs = 2 batch-tiles(64) x 64 j-tiles(8 j) ----
#define NBLK  128
#define NTHR  256      // 8 warps = kh(4) x mg(2, m32 each)
#define BJ    8
#define BB    64

// ---- SMEM layout (bytes) ----
// B weights: 40 n-rows (F0-7,I0-7,O0-7,C0-7,D0-7) x 512 k bf16, row 1040B
#define BROW   1040
#define SB_H   0
#define SB_L   41600
#define SA     83200          // A chunk bufs: 2 x 4 arrays x 64 rows x 272B
#define AROWB  272
#define AARR   17408          // 64*272
#define ABUF   69632          // 4 arrays
#define SMEM_SCAN 222464      // 83200 + 2*69632
// reduction region reuses buf0: 6 sets x 32 lanes x 41 floats
#define RLANE  41
#define RSET   1312           // 32*41 floats

// ---- device-global scratch ----
__device__ __nv_bfloat16 g_hh[2][BATCH][HDIM];
__device__ __nv_bfloat16 g_hl[2][BATCH][HDIM];
__device__ __nv_bfloat16 g_ch[2][BATCH][HDIM];
__device__ __nv_bfloat16 g_cl[2][BATCH][HDIM];
__device__ float g_c[2][BATCH][HDIM];
__device__ float g_u[SEQ][BATCH][G4];
__device__ unsigned g_bar[2];

// ---- helpers ----
static __device__ __forceinline__ uint32_t smem_u32(const void* p) {
    uint32_t a;
    asm("{ .reg .u64 t; cvta.to.shared.u64 t, %1; cvt.u32.u64 %0, t; }" : "=r"(a) : "l"(p));
    return a;
}
__device__ __forceinline__ void ldsm4(unsigned* r, uint32_t a) {
    asm volatile("ldmatrix.sync.aligned.m8n8.x4.shared.b16 {%0,%1,%2,%3}, [%4];"
        : "=r"(r[0]), "=r"(r[1]), "=r"(r[2]), "=r"(r[3]) : "r"(a));
}
__device__ __forceinline__ void ldsm2(unsigned* r, uint32_t a) {
    asm volatile("ldmatrix.sync.aligned.m8n8.x2.shared.b16 {%0,%1}, [%2];"
        : "=r"(r[0]), "=r"(r[1]) : "r"(a));
}
__device__ __forceinline__ void mma16816(float* d, const unsigned* a, const unsigned* b) {
    asm volatile("mma.sync.aligned.m16n8k16.row.col.f32.bf16.bf16.f32 "
        "{%0,%1,%2,%3}, {%4,%5,%6,%7}, {%8,%9}, {%0,%1,%2,%3};"
        : "+f"(d[0]), "+f"(d[1]), "+f"(d[2]), "+f"(d[3])
        : "r"(a[0]), "r"(a[1]), "r"(a[2]), "r"(a[3]), "r"(b[0]), "r"(b[1]));
}
__device__ __forceinline__ void cpa16(uint32_t dst, const void* src) {
    asm volatile("cp.async.cg.shared.global [%0], [%1], 16;" :: "r"(dst), "l"(src));
}
#define CP_COMMIT() asm volatile("cp.async.commit_group;" ::: "memory")
#define CP_WAIT(n)  asm volatile("cp.async.wait_group %0;" :: "n"(n) : "memory")

__device__ __forceinline__ unsigned long long fma2(unsigned long long a,
                                                   unsigned long long b,
                                                   unsigned long long c) {
    unsigned long long d;
    asm("fma.rn.f32x2 %0, %1, %2, %3;" : "=l"(d) : "l"(a), "l"(b), "l"(c));
    return d;
}
__device__ __forceinline__ float red2(unsigned long long a) {
    return __uint_as_float((unsigned)a) + __uint_as_float((unsigned)(a >> 32));
}
__device__ __forceinline__ float sigm(float x) { return 1.0f / (1.0f + __expf(-x)); }
__device__ __forceinline__ unsigned pack2(float a, float b) {
    return (unsigned)__bfloat16_as_ushort(__float2bfloat16(a)) |
           ((unsigned)__bfloat16_as_ushort(__float2bfloat16(b)) << 16);
}

// =====================================================================
// Kernel 1: u_pre = X @ U^T + Ub + Wallb  (gate biases folded)
// =====================================================================
__global__ void __launch_bounds__(128)
u_gemm_kernel(const float* __restrict__ X, const float* __restrict__ Uw,
              const float* __restrict__ Ub, const float* __restrict__ Wb) {
    __shared__ float As[64][36];
    __shared__ float Bs[64][36];
    const int g0 = blockIdx.x * 64;
    const int r0 = blockIdx.y * 64;
    const int tid = threadIdx.x;
    const int tx = tid & 7;
    const int ty = tid >> 3;

    unsigned long long acc[4][8] = {};

    for (int k0 = 0; k0 < IDIM; k0 += 32) {
#pragma unroll
        for (int q = 0; q < 4; ++q) {
            int idx = tid + q * 128;
            int row = idx >> 3;
            int c4  = (idx & 7) << 2;
            *(float4*)&As[row][c4] = *(const float4*)&X[(size_t)(r0 + row) * IDIM + k0 + c4];
            *(float4*)&Bs[row][c4] = *(const float4*)&Uw[(size_t)(g0 + row) * IDIM + k0 + c4];
        }
        __syncthreads();
#pragma unroll
        for (int k = 0; k < 32; k += 2) {
            unsigned long long a[4], b[8];
#pragma unroll
            for (int mi = 0; mi < 4; ++mi) a[mi] = *(const unsigned long long*)&As[ty * 4 + mi][k];
#pragma unroll
            for (int ni = 0; ni < 8; ++ni) b[ni] = *(const unsigned long long*)&Bs[tx + ni * 8][k];
#pragma unroll
            for (int mi = 0; mi < 4; ++mi)
#pragma unroll
                for (int ni = 0; ni < 8; ++ni)
                    acc[mi][ni] = fma2(a[mi], b[ni], acc[mi][ni]);
        }
        __syncthreads();
    }
#pragma unroll
    for (int mi = 0; mi < 4; ++mi) {
        int r = r0 + ty * 4 + mi;
        int b = r >> 9;
        int s = r & 511;
        float* orow = &g_u[s][b][0];
#pragma unroll
        for (int ni = 0; ni < 8; ++ni) {
            int g = g0 + tx + ni * 8;
            orow[g] = red2(acc[mi][ni]) + Ub[g] + Wb[g];
        }
    }
}

// =====================================================================
// Kernel 2: mma.sync (HMMA) scan. 128 CTAs x 256 thr.
// CTA = 64 batches x 8 j -> 40 output cols (F,I,O,C x8j + decay x8j).
// warp = kh(4 k-slices) x mg(2 m32-groups). 3-pass bf16 hi/lo MMA.
// State staged per 128-k chunk via cp.async double buffer. k-partials
// combined in SMEM; kh==0 warps run fp32 epilogue, write bf16 hi/lo state.
// =====================================================================
__global__ void __launch_bounds__(NTHR, 1)
timelstm_scan_mma(const float* __restrict__ Wall, const float* __restrict__ Wd,
                  const float* __restrict__ Wdb,  const float* __restrict__ ts,
                  float* __restrict__ out) {
    extern __shared__ char smc[];
    const uint32_t smb = smem_u32(smc);
    float* red = (float*)(smc + SA);

    const int tid  = threadIdx.x;
    const int lane = tid & 31;
    const int wid  = tid >> 5;
    const int kh   = wid >> 1;           // 0..3 k-slice
    const int mg   = wid & 1;            // 0..1 m32 group
    const int jt = blockIdx.x >> 1;
    const int bt = blockIdx.x & 1;
    const int j0 = jt * BJ;
    const int b0 = bt * BB;

    // ---- weights -> SMEM bf16 hi/lo, n-major rows (once) ----
    for (int idx = tid; idx < 40 * 128; idx += NTHR) {
        int n = idx >> 7;
        int k = (idx & 127) << 2;
        const float* sp = (n < 32)
            ? &Wall[(size_t)((n >> 3) * HDIM + j0 + (n & 7)) * HDIM + k]
            : &Wd[(size_t)(j0 + n - 32) * HDIM + k];
        float4 w = *(const float4*)sp;
        float wf[4] = {w.x, w.y, w.z, w.w};
        unsigned hi[2], lo[2];
#pragma unroll
        for (int p = 0; p < 2; ++p) {
            float a = wf[2*p], b = wf[2*p+1];
            __nv_bfloat16 ah = __float2bfloat16(a), bh = __float2bfloat16(b);
            float al = a - __bfloat162float(ah), bl = b - __bfloat162float(bh);
            hi[p] = (unsigned)__bfloat16_as_ushort(ah) | ((unsigned)__bfloat16_as_ushort(bh) << 16);
            lo[p] = pack2(al, bl);
        }
        *(uint2*)(smc + SB_H + n * BROW + k * 2) = make_uint2(hi[0], hi[1]);
        *(uint2*)(smc + SB_L + n * BROW + k * 2) = make_uint2(lo[0], lo[1]);
    }
    // decay bias for epilogue lanes
    const int tid4 = lane & 3, gid = lane >> 2;
    const int jc = 2 * tid4;
    float2 bdv = make_float2(0.f, 0.f);
    if (kh == 0) bdv = *(const float2*)&Wdb[j0 + jc];
    __syncthreads();

    // lane-dependent ldmatrix address pieces
    const uint32_t aoff = ((lane & 7) + ((lane >> 3) & 1) * 8) * AROWB + (lane >> 4) * 16;
    const uint32_t boff = (lane & 7) * BROW + ((lane >> 3) & 1) * 16 + (lane >> 4) * (8 * BROW);
    const uint32_t doff = (lane & 7) * BROW + ((lane >> 3) & 1) * 16;

    // staging mapping: 16 x 16B per thread per chunk
    const char* gsrc[4];
    gsrc[0] = (const char*)g_hh; gsrc[1] = (const char*)g_hl;
    gsrc[2] = (const char*)g_ch; gsrc[3] = (const char*)g_cl;

    for (int s = 0; s < SEQ; ++s) {
        const int cur = s & 1, nxt = cur ^ 1;
        const size_t curoff = (size_t)cur * BATCH * HDIM * 2;

        float dG[2][4][4] = {};
        float dD[2][4] = {};

        // ---- stage chunk 0 ----
#pragma unroll
        for (int t = 0; t < 16; ++t) {
            int idx = tid + t * NTHR;
            int arr = idx >> 10, rem = idx & 1023;
            int row = rem >> 4, seg = rem & 15;
            cpa16(smb + SA + arr * AARR + row * AROWB + seg * 16,
                  gsrc[arr] + curoff + (size_t)(b0 + row) * 1024 + seg * 16);
        }
        CP_COMMIT();

#pragma unroll 1
        for (int q = 0; q < 4; ++q) {
            const int buf = q & 1;
            if (q < 3) {
                const int nb = buf ^ 1;
#pragma unroll
                for (int t = 0; t < 16; ++t) {
                    int idx = tid + t * NTHR;
                    int arr = idx >> 10, rem = idx & 1023;
                    int row = rem >> 4, seg = rem & 15;
                    cpa16(smb + SA + nb * ABUF + arr * AARR + row * AROWB + seg * 16,
                          gsrc[arr] + curoff + (size_t)(b0 + row) * 1024 + (q + 1) * 256 + seg * 16);
                }
                CP_COMMIT();
                CP_WAIT(1);
            } else {
                CP_WAIT(0);
            }
            __syncthreads();

            const uint32_t abase = smb + SA + buf * ABUF;
#pragma unroll
            for (int kk = 0; kk < 2; ++kk) {
                const int ksl = kh * 2 + kk;               // kstep in chunk 0..7
                const uint32_t kbA = ksl * 32;
                const uint32_t kbB = q * 256 + ksl * 32;

                unsigned gh[8], gl[8], dh[2], dl[2];
                ldsm4(&gh[0], smb + SB_H + 0     + boff + kbB);   // F,I hi
                ldsm4(&gh[4], smb + SB_H + 16640 + boff + kbB);   // O,C hi
                ldsm4(&gl[0], smb + SB_L + 0     + boff + kbB);
                ldsm4(&gl[4], smb + SB_L + 16640 + boff + kbB);
                ldsm2(dh, smb + SB_H + 33280 + doff + kbB);       // D hi
                ldsm2(dl, smb + SB_L + 33280 + doff + kbB);

#pragma unroll
                for (int mt = 0; mt < 2; ++mt) {
                    const uint32_t rbase = (uint32_t)(mg * 32 + mt * 16) * AROWB + kbA + aoff;
                    unsigned ah[4], al[4], ch[4], cl[4];
                    ldsm4(ah, abase + 0 * AARR + rbase);
                    ldsm4(al, abase + 1 * AARR + rbase);
                    ldsm4(ch, abase + 2 * AARR + rbase);
                    ldsm4(cl, abase + 3 * AARR + rbase);
#pragma unroll
                    for (int nt = 0; nt < 4; ++nt) {
                        mma16816(dG[mt][nt], ah, &gh[nt * 2]);
                        mma16816(dG[mt][nt], ah, &gl[nt * 2]);
                        mma16816(dG[mt][nt], al, &gh[nt * 2]);
                    }
                    mma16816(dD[mt], ch, dh);
                    mma16816(dD[mt], ch, dl);
                    mma16816(dD[mt], cl, dh);
                }
            }
            __syncthreads();
        }

        // ---- k-partial exchange ----
        if (kh > 0) {
            float* rp = red + ((kh - 1) * 2 + mg) * RSET + lane * RLANE;
#pragma unroll
            for (int mt = 0; mt < 2; ++mt) {
#pragma unroll
                for (int nt = 0; nt < 4; ++nt)
#pragma unroll
                    for (int fr = 0; fr < 4; ++fr)
                        rp[mt * 20 + nt * 4 + fr] = dG[mt][nt][fr];
#pragma unroll
                for (int fr = 0; fr < 4; ++fr)
                    rp[mt * 20 + 16 + fr] = dD[mt][fr];
            }
        }
        __syncthreads();

        // ---- epilogue on kh==0 warps (wid 0,1) ----
        if (kh == 0) {
#pragma unroll
            for (int st = 0; st < 3; ++st) {
                const float* rp = red + (st * 2 + mg) * RSET + lane * RLANE;
#pragma unroll
                for (int mt = 0; mt < 2; ++mt) {
#pragma unroll
                    for (int nt = 0; nt < 4; ++nt)
#pragma unroll
                        for (int fr = 0; fr < 4; ++fr)
                            dG[mt][nt][fr] += rp[mt * 20 + nt * 4 + fr];
#pragma unroll
                    for (int fr = 0; fr < 4; ++fr)
                        dD[mt][fr] += rp[mt * 20 + 16 + fr];
                }
            }
#pragma unroll
            for (int mt = 0; mt < 2; ++mt) {
#pragma unroll
                for (int h2 = 0; h2 < 2; ++h2) {
                    const int b = b0 + mg * 32 + mt * 16 + gid + 8 * h2;
                    const float* ub = &g_u[s][b][0];
                    float2 uF = *(const float2*)(ub + 0 * HDIM + j0 + jc);
                    float2 uI = *(const float2*)(ub + 1 * HDIM + j0 + jc);
                    float2 uO = *(const float2*)(ub + 2 * HDIM + j0 + jc);
                    float2 uC = *(const float2*)(ub + 3 * HDIM + j0 + jc);
                    float2 co = *(const float2*)&g_c[cur][b][j0 + jc];
                    const float tv = ts[(size_t)b * SEQ + s];

                    float cn[2], hn[2];
#pragma unroll
                    for (int jj = 0; jj < 2; ++jj) {
                        const int fr = h2 * 2 + jj;
                        float F  = dG[mt][0][fr] + (jj ? uF.y : uF.x);
                        float I_ = dG[mt][1][fr] + (jj ? uI.y : uI.x);
                        float O_ = dG[mt][2][fr] + (jj ? uO.y : uO.x);
                        float Ct = dG[mt][3][fr] + (jj ? uC.y : uC.x);
                        float Dd = dD[mt][fr] + (jj ? bdv.y : bdv.x);
                        float f   = sigm(F);
                        float ii  = sigm(I_);
                        float oo  = sigm(O_);
                        float ct  = sigm(Ct);
                        float cs1 = tanhf(Dd);
                        float cadj = (jj ? co.y : co.x) + cs1 * (tv - 1.0f);
                        cn[jj] = f * cadj + ii * ct;
                        hn[jj] = oo * tanhf(cn[jj]);
                    }
                    *(float2*)&g_c[nxt][b][j0 + jc] = make_float2(cn[0], cn[1]);
                    *(float2*)&out[((size_t)b * SEQ + s) * HDIM + j0 + jc] =
                        make_float2(hn[0], hn[1]);
                    // bf16 hi/lo state
                    __nv_bfloat16 h0h = __float2bfloat16(hn[0]), h1h = __float2bfloat16(hn[1]);
                    __nv_bfloat16 c0h = __float2bfloat16(cn[0]), c1h = __float2bfloat16(cn[1]);
                    unsigned phh = (unsigned)__bfloat16_as_ushort(h0h) | ((unsigned)__bfloat16_as_ushort(h1h) << 16);
                    unsigned pch = (unsigned)__bfloat16_as_ushort(c0h) | ((unsigned)__bfloat16_as_ushort(c1h) << 16);
                    unsigned phl = pack2(hn[0] - __bfloat162float(h0h), hn[1] - __bfloat162float(h1h));
                    unsigned pcl = pack2(cn[0] - __bfloat162float(c0h), cn[1] - __bfloat162float(c1h));
                    *(unsigned*)&g_hh[nxt][b][j0 + jc] = phh;
                    *(unsigned*)&g_hl[nxt][b][j0 + jc] = phl;
                    *(unsigned*)&g_ch[nxt][b][j0 + jc] = pch;
                    *(unsigned*)&g_cl[nxt][b][j0 + jc] = pcl;
                }
            }
        }

        // ---- grid barrier ----
        __syncthreads();
        if (tid == 0) {
            volatile unsigned* vgen = &g_bar[1];
            unsigned gen = *vgen;
            __threadfence();
            if (atomicAdd(&g_bar[0], 1u) == NBLK - 1u) {
                g_bar[0] = 0u;
                __threadfence();
                *vgen = gen + 1u;
            } else {
                while (*vgen == gen) { }
            }
            __threadfence();
        }
        __syncthreads();
    }
}

// =====================================================================
extern "C" void kernel_launch(void* const* d_in, const int* in_sizes, int n_in,
                              void* d_out, int out_size) {
    const float* X     = (const float*)d_in[0];
    const float* T     = (const float*)d_in[1];
    const float* Wall  = (const float*)d_in[2];
    const float* Wallb = (const float*)d_in[3];
    const float* Uw    = (const float*)d_in[4];
    const float* Ubb   = (const float*)d_in[5];
    const float* Wd    = (const float*)d_in[6];
    const float* Wdb   = (const float*)d_in[7];
    float* out = (float*)d_out;

    void* p;
    cudaGetSymbolAddress(&p, g_hh); cudaMemsetAsync(p, 0, 2 * BATCH * HDIM * 2, 0);
    cudaGetSymbolAddress(&p, g_hl); cudaMemsetAsync(p, 0, 2 * BATCH * HDIM * 2, 0);
    cudaGetSymbolAddress(&p, g_ch); cudaMemsetAsync(p, 0, 2 * BATCH * HDIM * 2, 0);
    cudaGetSymbolAddress(&p, g_cl); cudaMemsetAsync(p, 0, 2 * BATCH * HDIM * 2, 0);
    cudaGetSymbolAddress(&p, g_c);  cudaMemsetAsync(p, 0, 2 * BATCH * HDIM * 4, 0);
    cudaGetSymbolAddress(&p, g_bar); cudaMemsetAsync(p, 0, 8, 0);

    dim3 ugrid(G4 / 64, (BATCH * SEQ) / 64);
    u_gemm_kernel<<<ugrid, 128>>>(X, Uw, Ubb, Wallb);

    cudaFuncSetAttribute(timelstm_scan_mma,
                         cudaFuncAttributeMaxDynamicSharedMemorySize, SMEM_SCAN);
    timelstm_scan_mma<<<NBLK, NTHR, SMEM_SCAN>>>(Wall, Wd, Wdb, T, out);
}

// round 13
// speedup vs baseline: 1.6669x; 1.2327x over previous
#include <cuda_runtime.h>
#include <cuda_bf16.h>
#include <cstdint>

#define BATCH 128
#define SEQ   512
#define IDIM  256
#define HDIM  512
#define G4    2048

// ---- scan geometry: 128 CTAs = 2 batch-tiles(64) x 64 j-tiles(8 j) ----
#define NBLK  128
#define NTHR  256      // 8 warps = kh(4) x mg(2, m32 each)
#define BJ    8
#define BB    64

// ---- SMEM layout (bytes) ----
#define BROW   1040
#define SB_H   0
#define SB_L   41600
#define SA     83200          // A chunk bufs: 2 x 4 arrays x 64 rows x 272B
#define AROWB  272
#define AARR   17408
#define ABUF   69632
#define SMEM_SCAN 222464
// canonical partials (reuse A buf0): 4 kh-sets x 64 b x 41 cols
#define RSETK  2624           // 64*41 floats

// ---- device-global scratch ----
__device__ __nv_bfloat16 g_hh[2][BATCH][HDIM];
__device__ __nv_bfloat16 g_hl[2][BATCH][HDIM];
__device__ __nv_bfloat16 g_ch[2][BATCH][HDIM];
__device__ __nv_bfloat16 g_cl[2][BATCH][HDIM];
__device__ float g_c[2][BATCH][HDIM];
__device__ float g_u[SEQ][BATCH][G4];
__device__ unsigned g_barx[8 * 32];     // group counters (128B apart)
__device__ unsigned g_barroot[32];      // [0]=root counter, [16]=generation

// ---- helpers ----
static __device__ __forceinline__ uint32_t smem_u32(const void* p) {
    uint32_t a;
    asm("{ .reg .u64 t; cvta.to.shared.u64 t, %1; cvt.u32.u64 %0, t; }" : "=r"(a) : "l"(p));
    return a;
}
__device__ __forceinline__ void ldsm4(unsigned* r, uint32_t a) {
    asm volatile("ldmatrix.sync.aligned.m8n8.x4.shared.b16 {%0,%1,%2,%3}, [%4];"
        : "=r"(r[0]), "=r"(r[1]), "=r"(r[2]), "=r"(r[3]) : "r"(a));
}
__device__ __forceinline__ void ldsm2(unsigned* r, uint32_t a) {
    asm volatile("ldmatrix.sync.aligned.m8n8.x2.shared.b16 {%0,%1}, [%2];"
        : "=r"(r[0]), "=r"(r[1]) : "r"(a));
}
__device__ __forceinline__ void mma16816(float* d, const unsigned* a, const unsigned* b) {
    asm volatile("mma.sync.aligned.m16n8k16.row.col.f32.bf16.bf16.f32 "
        "{%0,%1,%2,%3}, {%4,%5,%6,%7}, {%8,%9}, {%0,%1,%2,%3};"
        : "+f"(d[0]), "+f"(d[1]), "+f"(d[2]), "+f"(d[3])
        : "r"(a[0]), "r"(a[1]), "r"(a[2]), "r"(a[3]), "r"(b[0]), "r"(b[1]));
}
__device__ __forceinline__ void cpa16(uint32_t dst, const void* src) {
    asm volatile("cp.async.cg.shared.global [%0], [%1], 16;" :: "r"(dst), "l"(src));
}
#define CP_COMMIT() asm volatile("cp.async.commit_group;" ::: "memory")
#define CP_WAIT(n)  asm volatile("cp.async.wait_group %0;" :: "n"(n) : "memory")

__device__ __forceinline__ unsigned long long fma2(unsigned long long a,
                                                   unsigned long long b,
                                                   unsigned long long c) {
    unsigned long long d;
    asm("fma.rn.f32x2 %0, %1, %2, %3;" : "=l"(d) : "l"(a), "l"(b), "l"(c));
    return d;
}
__device__ __forceinline__ float red2(unsigned long long a) {
    return __uint_as_float((unsigned)a) + __uint_as_float((unsigned)(a >> 32));
}
__device__ __forceinline__ float sigm(float x) { return 1.0f / (1.0f + __expf(-x)); }
__device__ __forceinline__ float tanhfast(float x) {
    float y;
    asm("tanh.approx.f32 %0, %1;" : "=f"(y) : "f"(x));
    return y;
}
__device__ __forceinline__ unsigned pack2(float a, float b) {
    return (unsigned)__bfloat16_as_ushort(__float2bfloat16(a)) |
           ((unsigned)__bfloat16_as_ushort(__float2bfloat16(b)) << 16);
}

// =====================================================================
// Kernel 1: u_pre = X @ U^T + Ub + Wallb  (gate biases folded)
// =====================================================================
__global__ void __launch_bounds__(128)
u_gemm_kernel(const float* __restrict__ X, const float* __restrict__ Uw,
              const float* __restrict__ Ub, const float* __restrict__ Wb) {
    __shared__ float As[64][36];
    __shared__ float Bs[64][36];
    const int g0 = blockIdx.x * 64;
    const int r0 = blockIdx.y * 64;
    const int tid = threadIdx.x;
    const int tx = tid & 7;
    const int ty = tid >> 3;

    unsigned long long acc[4][8] = {};

    for (int k0 = 0; k0 < IDIM; k0 += 32) {
#pragma unroll
        for (int q = 0; q < 4; ++q) {
            int idx = tid + q * 128;
            int row = idx >> 3;
            int c4  = (idx & 7) << 2;
            *(float4*)&As[row][c4] = *(const float4*)&X[(size_t)(r0 + row) * IDIM + k0 + c4];
            *(float4*)&Bs[row][c4] = *(const float4*)&Uw[(size_t)(g0 + row) * IDIM + k0 + c4];
        }
        __syncthreads();
#pragma unroll
        for (int k = 0; k < 32; k += 2) {
            unsigned long long a[4], b[8];
#pragma unroll
            for (int mi = 0; mi < 4; ++mi) a[mi] = *(const unsigned long long*)&As[ty * 4 + mi][k];
#pragma unroll
            for (int ni = 0; ni < 8; ++ni) b[ni] = *(const unsigned long long*)&Bs[tx + ni * 8][k];
#pragma unroll
            for (int mi = 0; mi < 4; ++mi)
#pragma unroll
                for (int ni = 0; ni < 8; ++ni)
                    acc[mi][ni] = fma2(a[mi], b[ni], acc[mi][ni]);
        }
        __syncthreads();
    }
#pragma unroll
    for (int mi = 0; mi < 4; ++mi) {
        int r = r0 + ty * 4 + mi;
        int b = r >> 9;
        int s = r & 511;
        float* orow = &g_u[s][b][0];
#pragma unroll
        for (int ni = 0; ni < 8; ++ni) {
            int g = g0 + tx + ni * 8;
            orow[g] = red2(acc[mi][ni]) + Ub[g] + Wb[g];
        }
    }
}

// =====================================================================
// Kernel 2: mma.sync scan with latency-chain cuts:
//  - epilogue operands prefetched at step top (overlap DRAM with MMA)
//  - all 8 warps publish partials to canonical sred; all 256 threads
//    run the epilogue (1 batch x 2 j each)
//  - two-level grid barrier (8 groups x 16 CTAs, monotonic counters)
// =====================================================================
__global__ void __launch_bounds__(NTHR, 1)
timelstm_scan_mma(const float* __restrict__ Wall, const float* __restrict__ Wd,
                  const float* __restrict__ Wdb,  const float* __restrict__ ts,
                  float* __restrict__ out) {
    extern __shared__ char smc[];
    const uint32_t smb = smem_u32(smc);
    float* sred = (float*)(smc + SA);      // reuses A buf0 after last chunk

    const int tid  = threadIdx.x;
    const int lane = tid & 31;
    const int wid  = tid >> 5;
    const int kh   = wid >> 1;           // 0..3 k-slice
    const int mg   = wid & 1;            // 0..1 m32 group
    const int jt = blockIdx.x >> 1;
    const int bt = blockIdx.x & 1;
    const int j0 = jt * BJ;
    const int b0 = bt * BB;
    const int grp = blockIdx.x >> 4;     // barrier group 0..7

    // ---- weights -> SMEM bf16 hi/lo, n-major rows (once) ----
    for (int idx = tid; idx < 40 * 128; idx += NTHR) {
        int n = idx >> 7;
        int k = (idx & 127) << 2;
        const float* sp = (n < 32)
            ? &Wall[(size_t)((n >> 3) * HDIM + j0 + (n & 7)) * HDIM + k]
            : &Wd[(size_t)(j0 + n - 32) * HDIM + k];
        float4 w = *(const float4*)sp;
        float wf[4] = {w.x, w.y, w.z, w.w};
        unsigned hi[2], lo[2];
#pragma unroll
        for (int p = 0; p < 2; ++p) {
            float a = wf[2*p], b = wf[2*p+1];
            __nv_bfloat16 ah = __float2bfloat16(a), bh = __float2bfloat16(b);
            float al = a - __bfloat162float(ah), bl = b - __bfloat162float(bh);
            hi[p] = (unsigned)__bfloat16_as_ushort(ah) | ((unsigned)__bfloat16_as_ushort(bh) << 16);
            lo[p] = pack2(al, bl);
        }
        *(uint2*)(smc + SB_H + n * BROW + k * 2) = make_uint2(hi[0], hi[1]);
        *(uint2*)(smc + SB_L + n * BROW + k * 2) = make_uint2(lo[0], lo[1]);
    }

    // fragment lane pieces
    const int tid4 = lane & 3, gid = lane >> 2;
    // epilogue ownership: thread -> (1 batch, 2 j)
    const int bl_e = tid >> 2;                 // 0..63
    const int jp_e = tid & 3;                  // 0..3
    const int jc_e = 2 * jp_e;
    const int b_e  = b0 + bl_e;
    const float2 bdv = *(const float2*)&Wdb[j0 + jc_e];
    __syncthreads();

    // lane-dependent ldmatrix address pieces
    const uint32_t aoff = ((lane & 7) + ((lane >> 3) & 1) * 8) * AROWB + (lane >> 4) * 16;
    const uint32_t boff = (lane & 7) * BROW + ((lane >> 3) & 1) * 16 + (lane >> 4) * (8 * BROW);
    const uint32_t doff = (lane & 7) * BROW + ((lane >> 3) & 1) * 16;

    const char* gsrc[4];
    gsrc[0] = (const char*)g_hh; gsrc[1] = (const char*)g_hl;
    gsrc[2] = (const char*)g_ch; gsrc[3] = (const char*)g_cl;

    for (int s = 0; s < SEQ; ++s) {
        const int cur = s & 1, nxt = cur ^ 1;
        const size_t curoff = (size_t)cur * BATCH * HDIM * 2;

        // ---- prefetch epilogue operands (overlap with whole MMA phase) ----
        const float* ub = &g_u[s][b_e][0];
        float2 uF = __ldcg((const float2*)(ub + 0 * HDIM + j0 + jc_e));
        float2 uI = __ldcg((const float2*)(ub + 1 * HDIM + j0 + jc_e));
        float2 uO = __ldcg((const float2*)(ub + 2 * HDIM + j0 + jc_e));
        float2 uC = __ldcg((const float2*)(ub + 3 * HDIM + j0 + jc_e));
        float2 co = __ldcg((const float2*)&g_c[cur][b_e][j0 + jc_e]);
        const float tv = __ldcg(&ts[(size_t)b_e * SEQ + s]);

        float dG[2][4][4] = {};
        float dD[2][4] = {};

        // ---- stage chunk 0 ----
#pragma unroll
        for (int t = 0; t < 16; ++t) {
            int idx = tid + t * NTHR;
            int arr = idx >> 10, rem = idx & 1023;
            int row = rem >> 4, seg = rem & 15;
            cpa16(smb + SA + arr * AARR + row * AROWB + seg * 16,
                  gsrc[arr] + curoff + (size_t)(b0 + row) * 1024 + seg * 16);
        }
        CP_COMMIT();

#pragma unroll 1
        for (int q = 0; q < 4; ++q) {
            const int buf = q & 1;
            if (q < 3) {
                const int nb = buf ^ 1;
#pragma unroll
                for (int t = 0; t < 16; ++t) {
                    int idx = tid + t * NTHR;
                    int arr = idx >> 10, rem = idx & 1023;
                    int row = rem >> 4, seg = rem & 15;
                    cpa16(smb + SA + nb * ABUF + arr * AARR + row * AROWB + seg * 16,
                          gsrc[arr] + curoff + (size_t)(b0 + row) * 1024 + (q + 1) * 256 + seg * 16);
                }
                CP_COMMIT();
                CP_WAIT(1);
            } else {
                CP_WAIT(0);
            }
            __syncthreads();

            const uint32_t abase = smb + SA + buf * ABUF;
#pragma unroll
            for (int kk = 0; kk < 2; ++kk) {
                const int ksl = kh * 2 + kk;
                const uint32_t kbA = ksl * 32;
                const uint32_t kbB = q * 256 + ksl * 32;

                unsigned gh[8], gl[8], dh[2], dl[2];
                ldsm4(&gh[0], smb + SB_H + 0     + boff + kbB);
                ldsm4(&gh[4], smb + SB_H + 16640 + boff + kbB);
                ldsm4(&gl[0], smb + SB_L + 0     + boff + kbB);
                ldsm4(&gl[4], smb + SB_L + 16640 + boff + kbB);
                ldsm2(dh, smb + SB_H + 33280 + doff + kbB);
                ldsm2(dl, smb + SB_L + 33280 + doff + kbB);

#pragma unroll
                for (int mt = 0; mt < 2; ++mt) {
                    const uint32_t rbase = (uint32_t)(mg * 32 + mt * 16) * AROWB + kbA + aoff;
                    unsigned ah[4], al[4], ch[4], cl[4];
                    ldsm4(ah, abase + 0 * AARR + rbase);
                    ldsm4(al, abase + 1 * AARR + rbase);
                    ldsm4(ch, abase + 2 * AARR + rbase);
                    ldsm4(cl, abase + 3 * AARR + rbase);
#pragma unroll
                    for (int nt = 0; nt < 4; ++nt) {
                        mma16816(dG[mt][nt], ah, &gh[nt * 2]);
                        mma16816(dG[mt][nt], ah, &gl[nt * 2]);
                        mma16816(dG[mt][nt], al, &gh[nt * 2]);
                    }
                    mma16816(dD[mt], ch, dh);
                    mma16816(dD[mt], ch, dl);
                    mma16816(dD[mt], cl, dh);
                }
            }
            __syncthreads();
        }

        // ---- all warps publish partials to canonical (kh, b_loc, col) ----
        {
            float* rk = sred + kh * RSETK;
#pragma unroll
            for (int mt = 0; mt < 2; ++mt) {
                const int blr = mg * 32 + mt * 16 + gid;
#pragma unroll
                for (int fr = 0; fr < 4; ++fr) {
                    const int row = blr + (fr >> 1) * 8;
                    const int cp = tid4 * 2 + (fr & 1);
                    float* rr = rk + row * 41;
#pragma unroll
                    for (int nt = 0; nt < 4; ++nt)
                        rr[nt * 8 + cp] = dG[mt][nt][fr];
                    rr[32 + cp] = dD[mt][fr];
                }
            }
        }
        __syncthreads();

        // ---- epilogue: every thread finishes 1 batch x 2 j ----
        {
            float cn[2], hn[2];
            const float uFa[2] = {uF.x, uF.y}, uIa[2] = {uI.x, uI.y};
            const float uOa[2] = {uO.x, uO.y}, uCa[2] = {uC.x, uC.y};
            const float coa[2] = {co.x, co.y}, bda[2] = {bdv.x, bdv.y};
#pragma unroll
            for (int jj = 0; jj < 2; ++jj) {
                const int cb = jc_e + jj;
                float F = 0.f, I_ = 0.f, O_ = 0.f, Ct = 0.f, Dd = 0.f;
#pragma unroll
                for (int k4 = 0; k4 < 4; ++k4) {
                    const float* rr = sred + k4 * RSETK + bl_e * 41;
                    F  += rr[cb];
                    I_ += rr[8 + cb];
                    O_ += rr[16 + cb];
                    Ct += rr[24 + cb];
                    Dd += rr[32 + cb];
                }
                F  += uFa[jj];
                I_ += uIa[jj];
                O_ += uOa[jj];
                Ct += uCa[jj];
                Dd += bda[jj];
                float f   = sigm(F);
                float ii  = sigm(I_);
                float oo  = sigm(O_);
                float ct  = sigm(Ct);
                float cs1 = tanhfast(Dd);
                float cadj = coa[jj] + cs1 * (tv - 1.0f);   // c - cs1 + cs1*t
                cn[jj] = f * cadj + ii * ct;
                hn[jj] = oo * tanhfast(cn[jj]);
            }
            *(float2*)&g_c[nxt][b_e][j0 + jc_e] = make_float2(cn[0], cn[1]);
            *(float2*)&out[((size_t)b_e * SEQ + s) * HDIM + j0 + jc_e] =
                make_float2(hn[0], hn[1]);
            __nv_bfloat16 h0h = __float2bfloat16(hn[0]), h1h = __float2bfloat16(hn[1]);
            __nv_bfloat16 c0h = __float2bfloat16(cn[0]), c1h = __float2bfloat16(cn[1]);
            *(unsigned*)&g_hh[nxt][b_e][j0 + jc_e] =
                (unsigned)__bfloat16_as_ushort(h0h) | ((unsigned)__bfloat16_as_ushort(h1h) << 16);
            *(unsigned*)&g_ch[nxt][b_e][j0 + jc_e] =
                (unsigned)__bfloat16_as_ushort(c0h) | ((unsigned)__bfloat16_as_ushort(c1h) << 16);
            *(unsigned*)&g_hl[nxt][b_e][j0 + jc_e] =
                pack2(hn[0] - __bfloat162float(h0h), hn[1] - __bfloat162float(h1h));
            *(unsigned*)&g_cl[nxt][b_e][j0 + jc_e] =
                pack2(cn[0] - __bfloat162float(c0h), cn[1] - __bfloat162float(c1h));
        }

        // ---- two-level grid barrier (monotonic counters) ----
        __syncthreads();
        if (tid == 0) {
            volatile unsigned* vgen = &g_barroot[16];
            unsigned gen = *vgen;
            __threadfence();
            if (atomicAdd(&g_barx[grp * 32], 1u) == 16u * gen + 15u) {
                if (atomicAdd(&g_barroot[0], 1u) == 8u * gen + 7u) {
                    __threadfence();
                    *vgen = gen + 1u;
                }
            }
            while (*vgen == gen) { }
            __threadfence();
        }
        __syncthreads();
    }
}

// =====================================================================
extern "C" void kernel_launch(void* const* d_in, const int* in_sizes, int n_in,
                              void* d_out, int out_size) {
    const float* X     = (const float*)d_in[0];
    const float* T     = (const float*)d_in[1];
    const float* Wall  = (const float*)d_in[2];
    const float* Wallb = (const float*)d_in[3];
    const float* Uw    = (const float*)d_in[4];
    const float* Ubb   = (const float*)d_in[5];
    const float* Wd    = (const float*)d_in[6];
    const float* Wdb   = (const float*)d_in[7];
    float* out = (float*)d_out;

    void* p;
    cudaGetSymbolAddress(&p, g_hh); cudaMemsetAsync(p, 0, 2 * BATCH * HDIM * 2, 0);
    cudaGetSymbolAddress(&p, g_hl); cudaMemsetAsync(p, 0, 2 * BATCH * HDIM * 2, 0);
    cudaGetSymbolAddress(&p, g_ch); cudaMemsetAsync(p, 0, 2 * BATCH * HDIM * 2, 0);
    cudaGetSymbolAddress(&p, g_cl); cudaMemsetAsync(p, 0, 2 * BATCH * HDIM * 2, 0);
    cudaGetSymbolAddress(&p, g_c);  cudaMemsetAsync(p, 0, 2 * BATCH * HDIM * 4, 0);
    cudaGetSymbolAddress(&p, g_barx);    cudaMemsetAsync(p, 0, 8 * 32 * 4, 0);
    cudaGetSymbolAddress(&p, g_barroot); cudaMemsetAsync(p, 0, 32 * 4, 0);

    dim3 ugrid(G4 / 64, (BATCH * SEQ) / 64);
    u_gemm_kernel<<<ugrid, 128>>>(X, Uw, Ubb, Wallb);

    cudaFuncSetAttribute(timelstm_scan_mma,
                         cudaFuncAttributeMaxDynamicSharedMemorySize, SMEM_SCAN);
    timelstm_scan_mma<<<NBLK, NTHR, SMEM_SCAN>>>(Wall, Wd, Wdb, T, out);
}

// round 14
// speedup vs baseline: 1.7289x; 1.0372x over previous
#include <cuda_runtime.h>
#include <cuda_bf16.h>
#include <cstdint>

#define BATCH 128
#define SEQ   512
#define IDIM  256
#define HDIM  512
#define G4    2048

// ---- scan geometry: 128 CTAs = 2 batch-tiles(64) x 64 j-tiles(8 j) ----
#define NBLK  128
#define NTHR  256      // 8 warps = kh(4) x mg(2, m32 each)
#define BJ    8
#define BB    64

// ---- scan SMEM layout (bytes) ----
#define BROW   1040
#define SB_H   0
#define SB_L   41600
#define SA     83200          // A chunk bufs: 2 x 4 arrays x 64 rows x 272B
#define AROWB  272
#define AARR   17408
#define ABUF   69632
#define SMEM_SCAN 222464
#define RSETK  2624           // 64*41 floats

// ---- u_gemm (HMMA) SMEM layout ----
#define UG_AROW 528
#define UG_AHI  0
#define UG_ALO  67584
#define UG_BHI  135168
#define UG_BLO  168960
#define UG_SMEM 202752

// ---- device-global scratch ----
__device__ __nv_bfloat16 g_hh[2][BATCH][HDIM];
__device__ __nv_bfloat16 g_hl[2][BATCH][HDIM];
__device__ __nv_bfloat16 g_ch[2][BATCH][HDIM];
__device__ __nv_bfloat16 g_cl[2][BATCH][HDIM];
__device__ float g_c[2][BATCH][HDIM];
__device__ float g_u[SEQ][BATCH][G4];
__device__ unsigned g_barx[8 * 32];
__device__ unsigned g_barroot[32];

// ---- helpers ----
static __device__ __forceinline__ uint32_t smem_u32(const void* p) {
    uint32_t a;
    asm("{ .reg .u64 t; cvta.to.shared.u64 t, %1; cvt.u32.u64 %0, t; }" : "=r"(a) : "l"(p));
    return a;
}
__device__ __forceinline__ void ldsm4(unsigned* r, uint32_t a) {
    asm volatile("ldmatrix.sync.aligned.m8n8.x4.shared.b16 {%0,%1,%2,%3}, [%4];"
        : "=r"(r[0]), "=r"(r[1]), "=r"(r[2]), "=r"(r[3]) : "r"(a));
}
__device__ __forceinline__ void ldsm2(unsigned* r, uint32_t a) {
    asm volatile("ldmatrix.sync.aligned.m8n8.x2.shared.b16 {%0,%1}, [%2];"
        : "=r"(r[0]), "=r"(r[1]) : "r"(a));
}
__device__ __forceinline__ void mma16816(float* d, const unsigned* a, const unsigned* b) {
    asm volatile("mma.sync.aligned.m16n8k16.row.col.f32.bf16.bf16.f32 "
        "{%0,%1,%2,%3}, {%4,%5,%6,%7}, {%8,%9}, {%0,%1,%2,%3};"
        : "+f"(d[0]), "+f"(d[1]), "+f"(d[2]), "+f"(d[3])
        : "r"(a[0]), "r"(a[1]), "r"(a[2]), "r"(a[3]), "r"(b[0]), "r"(b[1]));
}
__device__ __forceinline__ void cpa16(uint32_t dst, const void* src) {
    asm volatile("cp.async.cg.shared.global [%0], [%1], 16;" :: "r"(dst), "l"(src));
}
#define CP_COMMIT() asm volatile("cp.async.commit_group;" ::: "memory")
#define CP_WAIT(n)  asm volatile("cp.async.wait_group %0;" :: "n"(n) : "memory")

__device__ __forceinline__ float sigm(float x) { return 1.0f / (1.0f + __expf(-x)); }
__device__ __forceinline__ float tanhfast(float x) {
    float y;
    asm("tanh.approx.f32 %0, %1;" : "=f"(y) : "f"(x));
    return y;
}
__device__ __forceinline__ unsigned pack2(float a, float b) {
    return (unsigned)__bfloat16_as_ushort(__float2bfloat16(a)) |
           ((unsigned)__bfloat16_as_ushort(__float2bfloat16(b)) << 16);
}
// fp32 pair -> bf16 hi/lo packed words
__device__ __forceinline__ void hilo2(float a, float b, unsigned& hi, unsigned& lo) {
    __nv_bfloat16 ah = __float2bfloat16(a), bh = __float2bfloat16(b);
    hi = (unsigned)__bfloat16_as_ushort(ah) | ((unsigned)__bfloat16_as_ushort(bh) << 16);
    lo = pack2(a - __bfloat162float(ah), b - __bfloat162float(bh));
}

// =====================================================================
// Kernel 1: u_pre = X @ U^T + Ub + Wallb, bf16 hi/lo 3-pass HMMA.
// Tile: M=128 x N=64 x K=256 (full K resident). 8 warps = 8 m16 tiles.
// =====================================================================
__global__ void __launch_bounds__(256)
u_gemm_mma(const float* __restrict__ X, const float* __restrict__ Uw,
           const float* __restrict__ Ub, const float* __restrict__ Wb) {
    extern __shared__ char smc[];
    const uint32_t smb = smem_u32(smc);
    const int tid  = threadIdx.x;
    const int lane = tid & 31;
    const int wid  = tid >> 5;
    const int g0 = blockIdx.x * 64;
    const int r0 = blockIdx.y * 128;

    // ---- stage A (X rows) fp32 -> bf16 hi/lo ----
#pragma unroll
    for (int t = 0; t < 32; ++t) {
        int idx = tid + t * 256;
        int row = idx >> 6, seg = idx & 63;
        float4 w = __ldcg((const float4*)&X[(size_t)(r0 + row) * IDIM + seg * 4]);
        unsigned h0, l0, h1, l1;
        hilo2(w.x, w.y, h0, l0);
        hilo2(w.z, w.w, h1, l1);
        *(uint2*)(smc + UG_AHI + row * UG_AROW + seg * 8) = make_uint2(h0, h1);
        *(uint2*)(smc + UG_ALO + row * UG_AROW + seg * 8) = make_uint2(l0, l1);
    }
    // ---- stage B (Uw rows) ----
#pragma unroll
    for (int t = 0; t < 16; ++t) {
        int idx = tid + t * 256;
        int row = idx >> 6, seg = idx & 63;
        float4 w = __ldcg((const float4*)&Uw[(size_t)(g0 + row) * IDIM + seg * 4]);
        unsigned h0, l0, h1, l1;
        hilo2(w.x, w.y, h0, l0);
        hilo2(w.z, w.w, h1, l1);
        *(uint2*)(smc + UG_BHI + row * UG_AROW + seg * 8) = make_uint2(h0, h1);
        *(uint2*)(smc + UG_BLO + row * UG_AROW + seg * 8) = make_uint2(l0, l1);
    }
    __syncthreads();

    const uint32_t aoff = ((lane & 7) + ((lane >> 3) & 1) * 8) * UG_AROW + (lane >> 4) * 16;
    const uint32_t boff = (lane & 7) * UG_AROW + ((lane >> 3) & 1) * 16 +
                          (lane >> 4) * (8 * UG_AROW);
    const uint32_t abase = smb + (uint32_t)(wid * 16) * UG_AROW;

    float d[8][4] = {};
#pragma unroll
    for (int ksl = 0; ksl < 16; ++ksl) {
        const uint32_t kb = ksl * 32;
        unsigned ah[4], al[4], bh[16], bl[16];
        ldsm4(ah, abase + UG_AHI + aoff + kb);
        ldsm4(al, abase + UG_ALO + aoff + kb);
#pragma unroll
        for (int n4 = 0; n4 < 4; ++n4) {
            ldsm4(&bh[n4 * 4], smb + UG_BHI + n4 * (16 * UG_AROW) + boff + kb);
            ldsm4(&bl[n4 * 4], smb + UG_BLO + n4 * (16 * UG_AROW) + boff + kb);
        }
#pragma unroll
        for (int nt = 0; nt < 8; ++nt) {
            const unsigned* fh = &bh[(nt >> 1) * 4 + (nt & 1) * 2];
            const unsigned* fl = &bl[(nt >> 1) * 4 + (nt & 1) * 2];
            mma16816(d[nt], ah, fh);
            mma16816(d[nt], ah, fl);
            mma16816(d[nt], al, fh);
        }
    }

    // ---- epilogue: fragment (gid,tid4) -> g_u[s][b][g] ----
    const int tid4 = lane & 3, gid = lane >> 2;
#pragma unroll
    for (int nt = 0; nt < 8; ++nt) {
        const int gb = g0 + nt * 8 + tid4 * 2;
        float2 bias = make_float2(Ub[gb] + Wb[gb], Ub[gb + 1] + Wb[gb + 1]);
#pragma unroll
        for (int h = 0; h < 2; ++h) {
            const int r = r0 + wid * 16 + gid + h * 8;
            const int b = r >> 9, s = r & 511;
            float2 v = make_float2(d[nt][h * 2] + bias.x, d[nt][h * 2 + 1] + bias.y);
            *(float2*)&g_u[s][b][gb] = v;
        }
    }
}

// =====================================================================
// Kernel 2: mma.sync scan (UNCHANGED from R13 best — 5.24 ms)
// =====================================================================
__global__ void __launch_bounds__(NTHR, 1)
timelstm_scan_mma(const float* __restrict__ Wall, const float* __restrict__ Wd,
                  const float* __restrict__ Wdb,  const float* __restrict__ ts,
                  float* __restrict__ out) {
    extern __shared__ char smc[];
    const uint32_t smb = smem_u32(smc);
    float* sred = (float*)(smc + SA);

    const int tid  = threadIdx.x;
    const int lane = tid & 31;
    const int wid  = tid >> 5;
    const int kh   = wid >> 1;
    const int mg   = wid & 1;
    const int jt = blockIdx.x >> 1;
    const int bt = blockIdx.x & 1;
    const int j0 = jt * BJ;
    const int b0 = bt * BB;
    const int grp = blockIdx.x >> 4;

    for (int idx = tid; idx < 40 * 128; idx += NTHR) {
        int n = idx >> 7;
        int k = (idx & 127) << 2;
        const float* sp = (n < 32)
            ? &Wall[(size_t)((n >> 3) * HDIM + j0 + (n & 7)) * HDIM + k]
            : &Wd[(size_t)(j0 + n - 32) * HDIM + k];
        float4 w = *(const float4*)sp;
        unsigned h0, l0, h1, l1;
        hilo2(w.x, w.y, h0, l0);
        hilo2(w.z, w.w, h1, l1);
        *(uint2*)(smc + SB_H + n * BROW + k * 2) = make_uint2(h0, h1);
        *(uint2*)(smc + SB_L + n * BROW + k * 2) = make_uint2(l0, l1);
    }

    const int tid4 = lane & 3, gid = lane >> 2;
    const int bl_e = tid >> 2;
    const int jp_e = tid & 3;
    const int jc_e = 2 * jp_e;
    const int b_e  = b0 + bl_e;
    const float2 bdv = *(const float2*)&Wdb[j0 + jc_e];
    __syncthreads();

    const uint32_t aoff = ((lane & 7) + ((lane >> 3) & 1) * 8) * AROWB + (lane >> 4) * 16;
    const uint32_t boff = (lane & 7) * BROW + ((lane >> 3) & 1) * 16 + (lane >> 4) * (8 * BROW);
    const uint32_t doff = (lane & 7) * BROW + ((lane >> 3) & 1) * 16;

    const char* gsrc[4];
    gsrc[0] = (const char*)g_hh; gsrc[1] = (const char*)g_hl;
    gsrc[2] = (const char*)g_ch; gsrc[3] = (const char*)g_cl;

    for (int s = 0; s < SEQ; ++s) {
        const int cur = s & 1, nxt = cur ^ 1;
        const size_t curoff = (size_t)cur * BATCH * HDIM * 2;

        const float* ub = &g_u[s][b_e][0];
        float2 uF = __ldcg((const float2*)(ub + 0 * HDIM + j0 + jc_e));
        float2 uI = __ldcg((const float2*)(ub + 1 * HDIM + j0 + jc_e));
        float2 uO = __ldcg((const float2*)(ub + 2 * HDIM + j0 + jc_e));
        float2 uC = __ldcg((const float2*)(ub + 3 * HDIM + j0 + jc_e));
        float2 co = __ldcg((const float2*)&g_c[cur][b_e][j0 + jc_e]);
        const float tv = __ldcg(&ts[(size_t)b_e * SEQ + s]);

        float dG[2][4][4] = {};
        float dD[2][4] = {};

#pragma unroll
        for (int t = 0; t < 16; ++t) {
            int idx = tid + t * NTHR;
            int arr = idx >> 10, rem = idx & 1023;
            int row = rem >> 4, seg = rem & 15;
            cpa16(smb + SA + arr * AARR + row * AROWB + seg * 16,
                  gsrc[arr] + curoff + (size_t)(b0 + row) * 1024 + seg * 16);
        }
        CP_COMMIT();

#pragma unroll 1
        for (int q = 0; q < 4; ++q) {
            const int buf = q & 1;
            if (q < 3) {
                const int nb = buf ^ 1;
#pragma unroll
                for (int t = 0; t < 16; ++t) {
                    int idx = tid + t * NTHR;
                    int arr = idx >> 10, rem = idx & 1023;
                    int row = rem >> 4, seg = rem & 15;
                    cpa16(smb + SA + nb * ABUF + arr * AARR + row * AROWB + seg * 16,
                          gsrc[arr] + curoff + (size_t)(b0 + row) * 1024 + (q + 1) * 256 + seg * 16);
                }
                CP_COMMIT();
                CP_WAIT(1);
            } else {
                CP_WAIT(0);
            }
            __syncthreads();

            const uint32_t abase = smb + SA + buf * ABUF;
#pragma unroll
            for (int kk = 0; kk < 2; ++kk) {
                const int ksl = kh * 2 + kk;
                const uint32_t kbA = ksl * 32;
                const uint32_t kbB = q * 256 + ksl * 32;

                unsigned gh[8], gl[8], dh[2], dl[2];
                ldsm4(&gh[0], smb + SB_H + 0     + boff + kbB);
                ldsm4(&gh[4], smb + SB_H + 16640 + boff + kbB);
                ldsm4(&gl[0], smb + SB_L + 0     + boff + kbB);
                ldsm4(&gl[4], smb + SB_L + 16640 + boff + kbB);
                ldsm2(dh, smb + SB_H + 33280 + doff + kbB);
                ldsm2(dl, smb + SB_L + 33280 + doff + kbB);

#pragma unroll
                for (int mt = 0; mt < 2; ++mt) {
                    const uint32_t rbase = (uint32_t)(mg * 32 + mt * 16) * AROWB + kbA + aoff;
                    unsigned ah[4], al[4], ch[4], cl[4];
                    ldsm4(ah, abase + 0 * AARR + rbase);
                    ldsm4(al, abase + 1 * AARR + rbase);
                    ldsm4(ch, abase + 2 * AARR + rbase);
                    ldsm4(cl, abase + 3 * AARR + rbase);
#pragma unroll
                    for (int nt = 0; nt < 4; ++nt) {
                        mma16816(dG[mt][nt], ah, &gh[nt * 2]);
                        mma16816(dG[mt][nt], ah, &gl[nt * 2]);
                        mma16816(dG[mt][nt], al, &gh[nt * 2]);
                    }
                    mma16816(dD[mt], ch, dh);
                    mma16816(dD[mt], ch, dl);
                    mma16816(dD[mt], cl, dh);
                }
            }
            __syncthreads();
        }

        {
            float* rk = sred + kh * RSETK;
#pragma unroll
            for (int mt = 0; mt < 2; ++mt) {
                const int blr = mg * 32 + mt * 16 + gid;
#pragma unroll
                for (int fr = 0; fr < 4; ++fr) {
                    const int row = blr + (fr >> 1) * 8;
                    const int cp = tid4 * 2 + (fr & 1);
                    float* rr = rk + row * 41;
#pragma unroll
                    for (int nt = 0; nt < 4; ++nt)
                        rr[nt * 8 + cp] = dG[mt][nt][fr];
                    rr[32 + cp] = dD[mt][fr];
                }
            }
        }
        __syncthreads();

        {
            float cn[2], hn[2];
            const float uFa[2] = {uF.x, uF.y}, uIa[2] = {uI.x, uI.y};
            const float uOa[2] = {uO.x, uO.y}, uCa[2] = {uC.x, uC.y};
            const float coa[2] = {co.x, co.y}, bda[2] = {bdv.x, bdv.y};
#pragma unroll
            for (int jj = 0; jj < 2; ++jj) {
                const int cb = jc_e + jj;
                float F = 0.f, I_ = 0.f, O_ = 0.f, Ct = 0.f, Dd = 0.f;
#pragma unroll
                for (int k4 = 0; k4 < 4; ++k4) {
                    const float* rr = sred + k4 * RSETK + bl_e * 41;
                    F  += rr[cb];
                    I_ += rr[8 + cb];
                    O_ += rr[16 + cb];
                    Ct += rr[24 + cb];
                    Dd += rr[32 + cb];
                }
                F  += uFa[jj];
                I_ += uIa[jj];
                O_ += uOa[jj];
                Ct += uCa[jj];
                Dd += bda[jj];
                float f   = sigm(F);
                float ii  = sigm(I_);
                float oo  = sigm(O_);
                float ct  = sigm(Ct);
                float cs1 = tanhfast(Dd);
                float cadj = coa[jj] + cs1 * (tv - 1.0f);
                cn[jj] = f * cadj + ii * ct;
                hn[jj] = oo * tanhfast(cn[jj]);
            }
            *(float2*)&g_c[nxt][b_e][j0 + jc_e] = make_float2(cn[0], cn[1]);
            *(float2*)&out[((size_t)b_e * SEQ + s) * HDIM + j0 + jc_e] =
                make_float2(hn[0], hn[1]);
            unsigned phh, phl, pch, pcl;
            hilo2(hn[0], hn[1], phh, phl);
            hilo2(cn[0], cn[1], pch, pcl);
            *(unsigned*)&g_hh[nxt][b_e][j0 + jc_e] = phh;
            *(unsigned*)&g_hl[nxt][b_e][j0 + jc_e] = phl;
            *(unsigned*)&g_ch[nxt][b_e][j0 + jc_e] = pch;
            *(unsigned*)&g_cl[nxt][b_e][j0 + jc_e] = pcl;
        }

        __syncthreads();
        if (tid == 0) {
            volatile unsigned* vgen = &g_barroot[16];
            unsigned gen = *vgen;
            __threadfence();
            if (atomicAdd(&g_barx[grp * 32], 1u) == 16u * gen + 15u) {
                if (atomicAdd(&g_barroot[0], 1u) == 8u * gen + 7u) {
                    __threadfence();
                    *vgen = gen + 1u;
                }
            }
            while (*vgen == gen) { }
            __threadfence();
        }
        __syncthreads();
    }
}

// =====================================================================
extern "C" void kernel_launch(void* const* d_in, const int* in_sizes, int n_in,
                              void* d_out, int out_size) {
    const float* X     = (const float*)d_in[0];
    const float* T     = (const float*)d_in[1];
    const float* Wall  = (const float*)d_in[2];
    const float* Wallb = (const float*)d_in[3];
    const float* Uw    = (const float*)d_in[4];
    const float* Ubb   = (const float*)d_in[5];
    const float* Wd    = (const float*)d_in[6];
    const float* Wdb   = (const float*)d_in[7];
    float* out = (float*)d_out;

    void* p;
    cudaGetSymbolAddress(&p, g_hh); cudaMemsetAsync(p, 0, 2 * BATCH * HDIM * 2, 0);
    cudaGetSymbolAddress(&p, g_hl); cudaMemsetAsync(p, 0, 2 * BATCH * HDIM * 2, 0);
    cudaGetSymbolAddress(&p, g_ch); cudaMemsetAsync(p, 0, 2 * BATCH * HDIM * 2, 0);
    cudaGetSymbolAddress(&p, g_cl); cudaMemsetAsync(p, 0, 2 * BATCH * HDIM * 2, 0);
    cudaGetSymbolAddress(&p, g_c);  cudaMemsetAsync(p, 0, 2 * BATCH * HDIM * 4, 0);
    cudaGetSymbolAddress(&p, g_barx);    cudaMemsetAsync(p, 0, 8 * 32 * 4, 0);
    cudaGetSymbolAddress(&p, g_barroot); cudaMemsetAsync(p, 0, 32 * 4, 0);

    cudaFuncSetAttribute(u_gemm_mma,
                         cudaFuncAttributeMaxDynamicSharedMemorySize, UG_SMEM);
    dim3 ugrid(G4 / 64, (BATCH * SEQ) / 128);
    u_gemm_mma<<<ugrid, 256, UG_SMEM>>>(X, Uw, Ubb, Wallb);

    cudaFuncSetAttribute(timelstm_scan_mma,
                         cudaFuncAttributeMaxDynamicSharedMemorySize, SMEM_SCAN);
    timelstm_scan_mma<<<NBLK, NTHR, SMEM_SCAN>>>(Wall, Wd, Wdb, T, out);
}

// round 15
// speedup vs baseline: 1.7785x; 1.0287x over previous
#include <cuda_runtime.h>
#include <cuda_bf16.h>
#include <cstdint>

#define BATCH 128
#define SEQ   512
#define IDIM  256
#define HDIM  512
#define G4    2048

// ---- scan geometry: 128 CTAs = 2 batch-tiles(64) x 64 j-tiles(8 j) ----
#define NBLK  128
#define NTHR  256      // 8 warps = kh(4) x mg(2, m32 each)
#define BJ    8
#define BB    64

// ---- scan SMEM layout (bytes) ----
#define BROW   1040
#define SB_H   0
#define SB_L   41600
#define SA     83200          // A chunk bufs: 2 x 4 arrays x 64 rows x 272B
#define AROWB  272
#define AARR   17408
#define ABUF   69632
#define SMEM_SCAN 222464
#define RSETK  2624           // 64*41 floats

// ---- u_gemm v2 SMEM layout (bytes) ----
#define UFS_X  0              // fp32 X staging: 2 bufs x 128 rows x 272B
#define UFS_U  69632          // fp32 U staging: 2 bufs x 64 rows x 272B
#define UBA    104448         // bf16 A hi (128 x 144B), lo at +18432
#define UBB    141312         // bf16 B hi (64 x 144B), lo at +9216
#define UG_SMEM 159744

// ---- device-global scratch ----
__device__ __nv_bfloat16 g_hh[2][BATCH][HDIM];
__device__ __nv_bfloat16 g_hl[2][BATCH][HDIM];
__device__ __nv_bfloat16 g_ch[2][BATCH][HDIM];
__device__ __nv_bfloat16 g_cl[2][BATCH][HDIM];
__device__ float g_c[2][BATCH][HDIM];
__device__ float g_u[SEQ][BATCH][G4];
__device__ unsigned g_barx[8 * 32];
__device__ unsigned g_barroot[32];

// ---- helpers ----
static __device__ __forceinline__ uint32_t smem_u32(const void* p) {
    uint32_t a;
    asm("{ .reg .u64 t; cvta.to.shared.u64 t, %1; cvt.u32.u64 %0, t; }" : "=r"(a) : "l"(p));
    return a;
}
__device__ __forceinline__ void ldsm4(unsigned* r, uint32_t a) {
    asm volatile("ldmatrix.sync.aligned.m8n8.x4.shared.b16 {%0,%1,%2,%3}, [%4];"
        : "=r"(r[0]), "=r"(r[1]), "=r"(r[2]), "=r"(r[3]) : "r"(a));
}
__device__ __forceinline__ void ldsm2(unsigned* r, uint32_t a) {
    asm volatile("ldmatrix.sync.aligned.m8n8.x2.shared.b16 {%0,%1}, [%2];"
        : "=r"(r[0]), "=r"(r[1]) : "r"(a));
}
__device__ __forceinline__ void mma16816(float* d, const unsigned* a, const unsigned* b) {
    asm volatile("mma.sync.aligned.m16n8k16.row.col.f32.bf16.bf16.f32 "
        "{%0,%1,%2,%3}, {%4,%5,%6,%7}, {%8,%9}, {%0,%1,%2,%3};"
        : "+f"(d[0]), "+f"(d[1]), "+f"(d[2]), "+f"(d[3])
        : "r"(a[0]), "r"(a[1]), "r"(a[2]), "r"(a[3]), "r"(b[0]), "r"(b[1]));
}
__device__ __forceinline__ void cpa16(uint32_t dst, const void* src) {
    asm volatile("cp.async.cg.shared.global [%0], [%1], 16;" :: "r"(dst), "l"(src));
}
#define CP_COMMIT() asm volatile("cp.async.commit_group;" ::: "memory")
#define CP_WAIT(n)  asm volatile("cp.async.wait_group %0;" :: "n"(n) : "memory")

__device__ __forceinline__ float sigm(float x) { return 1.0f / (1.0f + __expf(-x)); }
__device__ __forceinline__ float tanhfast(float x) {
    float y;
    asm("tanh.approx.f32 %0, %1;" : "=f"(y) : "f"(x));
    return y;
}
__device__ __forceinline__ unsigned pack2(float a, float b) {
    return (unsigned)__bfloat16_as_ushort(__float2bfloat16(a)) |
           ((unsigned)__bfloat16_as_ushort(__float2bfloat16(b)) << 16);
}
__device__ __forceinline__ void hilo2(float a, float b, unsigned& hi, unsigned& lo) {
    __nv_bfloat16 ah = __float2bfloat16(a), bh = __float2bfloat16(b);
    hi = (unsigned)__bfloat16_as_ushort(ah) | ((unsigned)__bfloat16_as_ushort(bh) << 16);
    lo = pack2(a - __bfloat162float(ah), b - __bfloat162float(bh));
}

// =====================================================================
// Kernel 1 v2: u_pre = X @ U^T + Ub + Wallb.
// K=256 in 4 chunks of 64. cp.async fp32 double-buffered staging,
// SMEM fp32 -> bf16 hi/lo conversion per chunk, 3-pass HMMA.
// Tile M=128 x N=64; 8 warps = 8 m16 tiles.
// =====================================================================
__global__ void __launch_bounds__(256)
u_gemm_mma(const float* __restrict__ X, const float* __restrict__ Uw,
           const float* __restrict__ Ub, const float* __restrict__ Wb) {
    extern __shared__ char smc[];
    const uint32_t smb = smem_u32(smc);
    const int tid  = threadIdx.x;
    const int lane = tid & 31;
    const int wid  = tid >> 5;
    const int g0 = blockIdx.x * 64;
    const int r0 = blockIdx.y * 128;

    // stage fp32 chunk q into fp32 buf b
    auto stage = [&](int q, int b) {
#pragma unroll
        for (int t = 0; t < 8; ++t) {            // X: 2048 16B units
            int idx = tid + t * 256;
            int row = idx >> 4, seg = idx & 15;
            cpa16(smb + UFS_X + b * 34816 + row * 272 + seg * 16,
                  &X[(size_t)(r0 + row) * IDIM + q * 64 + seg * 4]);
        }
#pragma unroll
        for (int t = 0; t < 4; ++t) {            // U: 1024 16B units
            int idx = tid + t * 256;
            int row = idx >> 4, seg = idx & 15;
            cpa16(smb + UFS_U + b * 17408 + row * 272 + seg * 16,
                  &Uw[(size_t)(g0 + row) * IDIM + q * 64 + seg * 4]);
        }
    };

    stage(0, 0); CP_COMMIT();
    stage(1, 1); CP_COMMIT();

    const uint32_t aoff = ((lane & 7) + ((lane >> 3) & 1) * 8) * 144 + (lane >> 4) * 16;
    const uint32_t boff = (lane & 7) * 144 + ((lane >> 3) & 1) * 16 + (lane >> 4) * (8 * 144);
    const uint32_t awoff = (uint32_t)(wid * 16) * 144 + aoff;

    float d[8][4] = {};

#pragma unroll
    for (int q = 0; q < 4; ++q) {
        const int buf = q & 1;
        if (q < 3) { CP_WAIT(1); } else { CP_WAIT(0); }
        __syncthreads();

        // ---- convert fp32 chunk -> bf16 hi/lo tiles ----
#pragma unroll
        for (int t = 0; t < 8; ++t) {            // A
            int idx = tid + t * 256;
            int row = idx >> 4, seg = idx & 15;
            float4 w = *(const float4*)(smc + UFS_X + buf * 34816 + row * 272 + seg * 16);
            unsigned h0, l0, h1, l1;
            hilo2(w.x, w.y, h0, l0);
            hilo2(w.z, w.w, h1, l1);
            *(uint2*)(smc + UBA + row * 144 + seg * 8)         = make_uint2(h0, h1);
            *(uint2*)(smc + UBA + 18432 + row * 144 + seg * 8) = make_uint2(l0, l1);
        }
#pragma unroll
        for (int t = 0; t < 4; ++t) {            // B
            int idx = tid + t * 256;
            int row = idx >> 4, seg = idx & 15;
            float4 w = *(const float4*)(smc + UFS_U + buf * 17408 + row * 272 + seg * 16);
            unsigned h0, l0, h1, l1;
            hilo2(w.x, w.y, h0, l0);
            hilo2(w.z, w.w, h1, l1);
            *(uint2*)(smc + UBB + row * 144 + seg * 8)        = make_uint2(h0, h1);
            *(uint2*)(smc + UBB + 9216 + row * 144 + seg * 8) = make_uint2(l0, l1);
        }
        __syncthreads();

        if (q < 2) { stage(q + 2, buf); CP_COMMIT(); }

        // ---- MMA on this chunk's bf16 tiles ----
#pragma unroll
        for (int ksl = 0; ksl < 4; ++ksl) {
            const uint32_t kb = ksl * 32;
            unsigned ah[4], al[4], bh[16], bl[16];
            ldsm4(ah, smb + UBA + awoff + kb);
            ldsm4(al, smb + UBA + 18432 + awoff + kb);
#pragma unroll
            for (int n4 = 0; n4 < 4; ++n4) {
                ldsm4(&bh[n4 * 4], smb + UBB + n4 * 2304 + boff + kb);
                ldsm4(&bl[n4 * 4], smb + UBB + 9216 + n4 * 2304 + boff + kb);
            }
#pragma unroll
            for (int nt = 0; nt < 8; ++nt) {
                const unsigned* fh = &bh[(nt >> 1) * 4 + (nt & 1) * 2];
                const unsigned* fl = &bl[(nt >> 1) * 4 + (nt & 1) * 2];
                mma16816(d[nt], ah, fh);
                mma16816(d[nt], ah, fl);
                mma16816(d[nt], al, fh);
            }
        }
    }

    // ---- epilogue: fragment (gid,tid4) -> g_u[s][b][g] ----
    const int tid4 = lane & 3, gid = lane >> 2;
#pragma unroll
    for (int nt = 0; nt < 8; ++nt) {
        const int gb = g0 + nt * 8 + tid4 * 2;
        float2 bias = make_float2(Ub[gb] + Wb[gb], Ub[gb + 1] + Wb[gb + 1]);
#pragma unroll
        for (int h = 0; h < 2; ++h) {
            const int r = r0 + wid * 16 + gid + h * 8;
            const int b = r >> 9, s = r & 511;
            float2 v = make_float2(d[nt][h * 2] + bias.x, d[nt][h * 2 + 1] + bias.y);
            *(float2*)&g_u[s][b][gb] = v;
        }
    }
}

// =====================================================================
// Kernel 2: mma.sync scan (R13 core; + cp.async-first step top,
// out[] store overlapped with barrier release)
// =====================================================================
__global__ void __launch_bounds__(NTHR, 1)
timelstm_scan_mma(const float* __restrict__ Wall, const float* __restrict__ Wd,
                  const float* __restrict__ Wdb,  const float* __restrict__ ts,
                  float* __restrict__ out) {
    extern __shared__ char smc[];
    const uint32_t smb = smem_u32(smc);
    float* sred = (float*)(smc + SA);

    const int tid  = threadIdx.x;
    const int lane = tid & 31;
    const int wid  = tid >> 5;
    const int kh   = wid >> 1;
    const int mg   = wid & 1;
    const int jt = blockIdx.x >> 1;
    const int bt = blockIdx.x & 1;
    const int j0 = jt * BJ;
    const int b0 = bt * BB;
    const int grp = blockIdx.x >> 4;

    for (int idx = tid; idx < 40 * 128; idx += NTHR) {
        int n = idx >> 7;
        int k = (idx & 127) << 2;
        const float* sp = (n < 32)
            ? &Wall[(size_t)((n >> 3) * HDIM + j0 + (n & 7)) * HDIM + k]
            : &Wd[(size_t)(j0 + n - 32) * HDIM + k];
        float4 w = *(const float4*)sp;
        unsigned h0, l0, h1, l1;
        hilo2(w.x, w.y, h0, l0);
        hilo2(w.z, w.w, h1, l1);
        *(uint2*)(smc + SB_H + n * BROW + k * 2) = make_uint2(h0, h1);
        *(uint2*)(smc + SB_L + n * BROW + k * 2) = make_uint2(l0, l1);
    }

    const int tid4 = lane & 3, gid = lane >> 2;
    const int bl_e = tid >> 2;
    const int jp_e = tid & 3;
    const int jc_e = 2 * jp_e;
    const int b_e  = b0 + bl_e;
    const float2 bdv = *(const float2*)&Wdb[j0 + jc_e];
    __syncthreads();

    const uint32_t aoff = ((lane & 7) + ((lane >> 3) & 1) * 8) * AROWB + (lane >> 4) * 16;
    const uint32_t boff = (lane & 7) * BROW + ((lane >> 3) & 1) * 16 + (lane >> 4) * (8 * BROW);
    const uint32_t doff = (lane & 7) * BROW + ((lane >> 3) & 1) * 16;

    const char* gsrc[4];
    gsrc[0] = (const char*)g_hh; gsrc[1] = (const char*)g_hl;
    gsrc[2] = (const char*)g_ch; gsrc[3] = (const char*)g_cl;

    for (int s = 0; s < SEQ; ++s) {
        const int cur = s & 1, nxt = cur ^ 1;
        const size_t curoff = (size_t)cur * BATCH * HDIM * 2;

        // ---- chunk-0 staging FIRST (critical path), then u prefetch ----
#pragma unroll
        for (int t = 0; t < 16; ++t) {
            int idx = tid + t * NTHR;
            int arr = idx >> 10, rem = idx & 1023;
            int row = rem >> 4, seg = rem & 15;
            cpa16(smb + SA + arr * AARR + row * AROWB + seg * 16,
                  gsrc[arr] + curoff + (size_t)(b0 + row) * 1024 + seg * 16);
        }
        CP_COMMIT();

        const float* ub = &g_u[s][b_e][0];
        float2 uF = __ldcg((const float2*)(ub + 0 * HDIM + j0 + jc_e));
        float2 uI = __ldcg((const float2*)(ub + 1 * HDIM + j0 + jc_e));
        float2 uO = __ldcg((const float2*)(ub + 2 * HDIM + j0 + jc_e));
        float2 uC = __ldcg((const float2*)(ub + 3 * HDIM + j0 + jc_e));
        float2 co = __ldcg((const float2*)&g_c[cur][b_e][j0 + jc_e]);
        const float tv = __ldcg(&ts[(size_t)b_e * SEQ + s]);

        float dG[2][4][4] = {};
        float dD[2][4] = {};

#pragma unroll 1
        for (int q = 0; q < 4; ++q) {
            const int buf = q & 1;
            if (q < 3) {
                const int nb = buf ^ 1;
#pragma unroll
                for (int t = 0; t < 16; ++t) {
                    int idx = tid + t * NTHR;
                    int arr = idx >> 10, rem = idx & 1023;
                    int row = rem >> 4, seg = rem & 15;
                    cpa16(smb + SA + nb * ABUF + arr * AARR + row * AROWB + seg * 16,
                          gsrc[arr] + curoff + (size_t)(b0 + row) * 1024 + (q + 1) * 256 + seg * 16);
                }
                CP_COMMIT();
                CP_WAIT(1);
            } else {
                CP_WAIT(0);
            }
            __syncthreads();

            const uint32_t abase = smb + SA + buf * ABUF;
#pragma unroll
            for (int kk = 0; kk < 2; ++kk) {
                const int ksl = kh * 2 + kk;
                const uint32_t kbA = ksl * 32;
                const uint32_t kbB = q * 256 + ksl * 32;

                unsigned gh[8], gl[8], dh[2], dl[2];
                ldsm4(&gh[0], smb + SB_H + 0     + boff + kbB);
                ldsm4(&gh[4], smb + SB_H + 16640 + boff + kbB);
                ldsm4(&gl[0], smb + SB_L + 0     + boff + kbB);
                ldsm4(&gl[4], smb + SB_L + 16640 + boff + kbB);
                ldsm2(dh, smb + SB_H + 33280 + doff + kbB);
                ldsm2(dl, smb + SB_L + 33280 + doff + kbB);

#pragma unroll
                for (int mt = 0; mt < 2; ++mt) {
                    const uint32_t rbase = (uint32_t)(mg * 32 + mt * 16) * AROWB + kbA + aoff;
                    unsigned ah[4], al[4], ch[4], cl[4];
                    ldsm4(ah, abase + 0 * AARR + rbase);
                    ldsm4(al, abase + 1 * AARR + rbase);
                    ldsm4(ch, abase + 2 * AARR + rbase);
                    ldsm4(cl, abase + 3 * AARR + rbase);
#pragma unroll
                    for (int nt = 0; nt < 4; ++nt) {
                        mma16816(dG[mt][nt], ah, &gh[nt * 2]);
                        mma16816(dG[mt][nt], ah, &gl[nt * 2]);
                        mma16816(dG[mt][nt], al, &gh[nt * 2]);
                    }
                    mma16816(dD[mt], ch, dh);
                    mma16816(dD[mt], ch, dl);
                    mma16816(dD[mt], cl, dh);
                }
            }
            __syncthreads();
        }

        {
            float* rk = sred + kh * RSETK;
#pragma unroll
            for (int mt = 0; mt < 2; ++mt) {
                const int blr = mg * 32 + mt * 16 + gid;
#pragma unroll
                for (int fr = 0; fr < 4; ++fr) {
                    const int row = blr + (fr >> 1) * 8;
                    const int cp = tid4 * 2 + (fr & 1);
                    float* rr = rk + row * 41;
#pragma unroll
                    for (int nt = 0; nt < 4; ++nt)
                        rr[nt * 8 + cp] = dG[mt][nt][fr];
                    rr[32 + cp] = dD[mt][fr];
                }
            }
        }
        __syncthreads();

        float hn0, hn1;
        {
            float cn[2], hn[2];
            const float uFa[2] = {uF.x, uF.y}, uIa[2] = {uI.x, uI.y};
            const float uOa[2] = {uO.x, uO.y}, uCa[2] = {uC.x, uC.y};
            const float coa[2] = {co.x, co.y}, bda[2] = {bdv.x, bdv.y};
#pragma unroll
            for (int jj = 0; jj < 2; ++jj) {
                const int cb = jc_e + jj;
                float F = 0.f, I_ = 0.f, O_ = 0.f, Ct = 0.f, Dd = 0.f;
#pragma unroll
                for (int k4 = 0; k4 < 4; ++k4) {
                    const float* rr = sred + k4 * RSETK + bl_e * 41;
                    F  += rr[cb];
                    I_ += rr[8 + cb];
                    O_ += rr[16 + cb];
                    Ct += rr[24 + cb];
                    Dd += rr[32 + cb];
                }
                F  += uFa[jj];
                I_ += uIa[jj];
                O_ += uOa[jj];
                Ct += uCa[jj];
                Dd += bda[jj];
                float f   = sigm(F);
                float ii  = sigm(I_);
                float oo  = sigm(O_);
                float ct  = sigm(Ct);
                float cs1 = tanhfast(Dd);
                float cadj = coa[jj] + cs1 * (tv - 1.0f);
                cn[jj] = f * cadj + ii * ct;
                hn[jj] = oo * tanhfast(cn[jj]);
            }
            // state writes (must precede barrier arrive)
            *(float2*)&g_c[nxt][b_e][j0 + jc_e] = make_float2(cn[0], cn[1]);
            unsigned phh, phl, pch, pcl;
            hilo2(hn[0], hn[1], phh, phl);
            hilo2(cn[0], cn[1], pch, pcl);
            *(unsigned*)&g_hh[nxt][b_e][j0 + jc_e] = phh;
            *(unsigned*)&g_hl[nxt][b_e][j0 + jc_e] = phl;
            *(unsigned*)&g_ch[nxt][b_e][j0 + jc_e] = pch;
            *(unsigned*)&g_cl[nxt][b_e][j0 + jc_e] = pcl;
            hn0 = hn[0]; hn1 = hn[1];
        }

        // ---- barrier arrive, out[] store overlapped with release wait ----
        __syncthreads();
        unsigned gen = 0;
        if (tid == 0) {
            gen = *(volatile unsigned*)&g_barroot[16];
            __threadfence();
            if (atomicAdd(&g_barx[grp * 32], 1u) == 16u * gen + 15u) {
                if (atomicAdd(&g_barroot[0], 1u) == 8u * gen + 7u) {
                    __threadfence();
                    *(volatile unsigned*)&g_barroot[16] = gen + 1u;
                }
            }
        }
        *(float2*)&out[((size_t)b_e * SEQ + s) * HDIM + j0 + jc_e] = make_float2(hn0, hn1);
        if (tid == 0) {
            volatile unsigned* vgen = &g_barroot[16];
            while (*vgen == gen) { }
            __threadfence();
        }
        __syncthreads();
    }
}

// =====================================================================
extern "C" void kernel_launch(void* const* d_in, const int* in_sizes, int n_in,
                              void* d_out, int out_size) {
    const float* X     = (const float*)d_in[0];
    const float* T     = (const float*)d_in[1];
    const float* Wall  = (const float*)d_in[2];
    const float* Wallb = (const float*)d_in[3];
    const float* Uw    = (const float*)d_in[4];
    const float* Ubb   = (const float*)d_in[5];
    const float* Wd    = (const float*)d_in[6];
    const float* Wdb   = (const float*)d_in[7];
    float* out = (float*)d_out;

    void* p;
    cudaGetSymbolAddress(&p, g_hh); cudaMemsetAsync(p, 0, 2 * BATCH * HDIM * 2, 0);
    cudaGetSymbolAddress(&p, g_hl); cudaMemsetAsync(p, 0, 2 * BATCH * HDIM * 2, 0);
    cudaGetSymbolAddress(&p, g_ch); cudaMemsetAsync(p, 0, 2 * BATCH * HDIM * 2, 0);
    cudaGetSymbolAddress(&p, g_cl); cudaMemsetAsync(p, 0, 2 * BATCH * HDIM * 2, 0);
    cudaGetSymbolAddress(&p, g_c);  cudaMemsetAsync(p, 0, 2 * BATCH * HDIM * 4, 0);
    cudaGetSymbolAddress(&p, g_barx);    cudaMemsetAsync(p, 0, 8 * 32 * 4, 0);
    cudaGetSymbolAddress(&p, g_barroot); cudaMemsetAsync(p, 0, 32 * 4, 0);

    cudaFuncSetAttribute(u_gemm_mma,
                         cudaFuncAttributeMaxDynamicSharedMemorySize, UG_SMEM);
    dim3 ugrid(G4 / 64, (BATCH * SEQ) / 128);
    u_gemm_mma<<<ugrid, 256, UG_SMEM>>>(X, Uw, Ubb, Wallb);

    cudaFuncSetAttribute(timelstm_scan_mma,
                         cudaFuncAttributeMaxDynamicSharedMemorySize, SMEM_SCAN);
    timelstm_scan_mma<<<NBLK, NTHR, SMEM_SCAN>>>(Wall, Wd, Wdb, T, out);
}

// round 16
// speedup vs baseline: 1.9188x; 1.0789x over previous
#include <cuda_runtime.h>
#include <cuda_bf16.h>
#include <cstdint>

#define BATCH 128
#define SEQ   512
#define IDIM  256
#define HDIM  512
#define G4    2048

// ---- scan geometry: 128 CTAs = 2 batch-tiles(64) x 64 j-tiles(8 j) ----
#define NBLK  128
#define NTHR  256      // 8 warps = kh(4) x mg(2, m32 each)
#define BJ    8
#define BB    64

// ---- scan SMEM layout (bytes) ----
#define BROW   1040
#define SB_H   0
#define SB_L   41600
#define SA     83200          // A chunk bufs: 2 x 4 arrays x 64 rows x 272B
#define AROWB  272
#define AARR   17408
#define ABUF   69632
#define SMEM_SCAN 222464
#define RSETK  2624           // 64*41 floats

// ---- u_gemm v3 SMEM layout (bytes): K chunks of 32, 84KB -> 2 CTAs/SM ----
#define UFS_X  0              // fp32 X staging: 2 bufs x 128 rows x 144B
#define UFS_U  36864          // fp32 U staging: 2 bufs x 64 rows x 144B
#define UBA    55296          // bf16 A hi (128 x 80B), lo at +10240
#define UBB    75776          // bf16 B hi (64 x 80B), lo at +5120
#define UG_SMEM 86016

// ---- device-global scratch ----
__device__ __nv_bfloat16 g_hh[2][BATCH][HDIM];
__device__ __nv_bfloat16 g_hl[2][BATCH][HDIM];
__device__ __nv_bfloat16 g_ch[2][BATCH][HDIM];
__device__ __nv_bfloat16 g_cl[2][BATCH][HDIM];
__device__ float g_c[2][BATCH][HDIM];
__device__ float g_u[SEQ][BATCH][G4];
__device__ unsigned g_barx[8 * 32];     // (bt*4+sub)*32: 8 group counters
__device__ unsigned g_barroot[64];      // per-bt: [bt*32]=root, [bt*32+16]=gen

// ---- helpers ----
static __device__ __forceinline__ uint32_t smem_u32(const void* p) {
    uint32_t a;
    asm("{ .reg .u64 t; cvta.to.shared.u64 t, %1; cvt.u32.u64 %0, t; }" : "=r"(a) : "l"(p));
    return a;
}
__device__ __forceinline__ void ldsm4(unsigned* r, uint32_t a) {
    asm volatile("ldmatrix.sync.aligned.m8n8.x4.shared.b16 {%0,%1,%2,%3}, [%4];"
        : "=r"(r[0]), "=r"(r[1]), "=r"(r[2]), "=r"(r[3]) : "r"(a));
}
__device__ __forceinline__ void ldsm2(unsigned* r, uint32_t a) {
    asm volatile("ldmatrix.sync.aligned.m8n8.x2.shared.b16 {%0,%1}, [%2];"
        : "=r"(r[0]), "=r"(r[1]) : "r"(a));
}
__device__ __forceinline__ void mma16816(float* d, const unsigned* a, const unsigned* b) {
    asm volatile("mma.sync.aligned.m16n8k16.row.col.f32.bf16.bf16.f32 "
        "{%0,%1,%2,%3}, {%4,%5,%6,%7}, {%8,%9}, {%0,%1,%2,%3};"
        : "+f"(d[0]), "+f"(d[1]), "+f"(d[2]), "+f"(d[3])
        : "r"(a[0]), "r"(a[1]), "r"(a[2]), "r"(a[3]), "r"(b[0]), "r"(b[1]));
}
__device__ __forceinline__ void cpa16(uint32_t dst, const void* src) {
    asm volatile("cp.async.cg.shared.global [%0], [%1], 16;" :: "r"(dst), "l"(src));
}
#define CP_COMMIT() asm volatile("cp.async.commit_group;" ::: "memory")
#define CP_WAIT(n)  asm volatile("cp.async.wait_group %0;" :: "n"(n) : "memory")

__device__ __forceinline__ float sigm(float x) { return 1.0f / (1.0f + __expf(-x)); }
__device__ __forceinline__ float tanhfast(float x) {
    float y;
    asm("tanh.approx.f32 %0, %1;" : "=f"(y) : "f"(x));
    return y;
}
__device__ __forceinline__ unsigned pack2(float a, float b) {
    return (unsigned)__bfloat16_as_ushort(__float2bfloat16(a)) |
           ((unsigned)__bfloat16_as_ushort(__float2bfloat16(b)) << 16);
}
__device__ __forceinline__ void hilo2(float a, float b, unsigned& hi, unsigned& lo) {
    __nv_bfloat16 ah = __float2bfloat16(a), bh = __float2bfloat16(b);
    hi = (unsigned)__bfloat16_as_ushort(ah) | ((unsigned)__bfloat16_as_ushort(bh) << 16);
    lo = pack2(a - __bfloat162float(ah), b - __bfloat162float(bh));
}

// =====================================================================
// Kernel 1 v3: u_pre = X @ U^T + Ub + Wallb.
// K=256 in 8 chunks of 32. 84KB SMEM -> 2 CTAs/SM (cross-CTA overlap).
// cp.async fp32 double-buffer, SMEM fp32->bf16 hi/lo, 3-pass HMMA.
// =====================================================================
__global__ void __launch_bounds__(256, 2)
u_gemm_mma(const float* __restrict__ X, const float* __restrict__ Uw,
           const float* __restrict__ Ub, const float* __restrict__ Wb) {
    extern __shared__ char smc[];
    const uint32_t smb = smem_u32(smc);
    const int tid  = threadIdx.x;
    const int lane = tid & 31;
    const int wid  = tid >> 5;
    const int g0 = blockIdx.x * 64;
    const int r0 = blockIdx.y * 128;

    auto stage = [&](int q, int b) {
#pragma unroll
        for (int t = 0; t < 4; ++t) {            // X: 1024 16B units
            int idx = tid + t * 256;
            int row = idx >> 3, seg = idx & 7;
            cpa16(smb + UFS_X + b * 18432 + row * 144 + seg * 16,
                  &X[(size_t)(r0 + row) * IDIM + q * 32 + seg * 4]);
        }
#pragma unroll
        for (int t = 0; t < 2; ++t) {            // U: 512 16B units
            int idx = tid + t * 256;
            int row = idx >> 3, seg = idx & 7;
            cpa16(smb + UFS_U + b * 9216 + row * 144 + seg * 16,
                  &Uw[(size_t)(g0 + row) * IDIM + q * 32 + seg * 4]);
        }
    };

    stage(0, 0); CP_COMMIT();
    stage(1, 1); CP_COMMIT();

    const uint32_t aoff = ((lane & 7) + ((lane >> 3) & 1) * 8) * 80 + (lane >> 4) * 16;
    const uint32_t boff = (lane & 7) * 80 + ((lane >> 3) & 1) * 16 + (lane >> 4) * (8 * 80);
    const uint32_t awoff = (uint32_t)(wid * 16) * 80 + aoff;

    float d[8][4] = {};

#pragma unroll 1
    for (int q = 0; q < 8; ++q) {
        const int buf = q & 1;
        if (q < 7) { CP_WAIT(1); } else { CP_WAIT(0); }
        __syncthreads();

        // ---- convert fp32 chunk -> bf16 hi/lo tiles ----
#pragma unroll
        for (int t = 0; t < 4; ++t) {            // A: 1024 float4
            int idx = tid + t * 256;
            int row = idx >> 3, seg = idx & 7;
            float4 w = *(const float4*)(smc + UFS_X + buf * 18432 + row * 144 + seg * 16);
            unsigned h0, l0, h1, l1;
            hilo2(w.x, w.y, h0, l0);
            hilo2(w.z, w.w, h1, l1);
            *(uint2*)(smc + UBA + row * 80 + seg * 8)         = make_uint2(h0, h1);
            *(uint2*)(smc + UBA + 10240 + row * 80 + seg * 8) = make_uint2(l0, l1);
        }
#pragma unroll
        for (int t = 0; t < 2; ++t) {            // B: 512 float4
            int idx = tid + t * 256;
            int row = idx >> 3, seg = idx & 7;
            float4 w = *(const float4*)(smc + UFS_U + buf * 9216 + row * 144 + seg * 16);
            unsigned h0, l0, h1, l1;
            hilo2(w.x, w.y, h0, l0);
            hilo2(w.z, w.w, h1, l1);
            *(uint2*)(smc + UBB + row * 80 + seg * 8)        = make_uint2(h0, h1);
            *(uint2*)(smc + UBB + 5120 + row * 80 + seg * 8) = make_uint2(l0, l1);
        }
        __syncthreads();

        if (q < 6) { stage(q + 2, buf); CP_COMMIT(); }

        // ---- MMA on this chunk's bf16 tiles (K=32 -> 2 k16 steps) ----
#pragma unroll
        for (int ksl = 0; ksl < 2; ++ksl) {
            const uint32_t kb = ksl * 32;
            unsigned ah[4], al[4], bh[16], bl[16];
            ldsm4(ah, smb + UBA + awoff + kb);
            ldsm4(al, smb + UBA + 10240 + awoff + kb);
#pragma unroll
            for (int n4 = 0; n4 < 4; ++n4) {
                ldsm4(&bh[n4 * 4], smb + UBB + n4 * (16 * 80) + boff + kb);
                ldsm4(&bl[n4 * 4], smb + UBB + 5120 + n4 * (16 * 80) + boff + kb);
            }
#pragma unroll
            for (int nt = 0; nt < 8; ++nt) {
                const unsigned* fh = &bh[(nt >> 1) * 4 + (nt & 1) * 2];
                const unsigned* fl = &bl[(nt >> 1) * 4 + (nt & 1) * 2];
                mma16816(d[nt], ah, fh);
                mma16816(d[nt], ah, fl);
                mma16816(d[nt], al, fh);
            }
        }
        __syncthreads();   // protect bf16 tiles (single-buffered) for next chunk
    }

    // ---- epilogue: fragment (gid,tid4) -> g_u[s][b][g] ----
    const int tid4 = lane & 3, gid = lane >> 2;
#pragma unroll
    for (int nt = 0; nt < 8; ++nt) {
        const int gb = g0 + nt * 8 + tid4 * 2;
        float2 bias = make_float2(Ub[gb] + Wb[gb], Ub[gb + 1] + Wb[gb + 1]);
#pragma unroll
        for (int h = 0; h < 2; ++h) {
            const int r = r0 + wid * 16 + gid + h * 8;
            const int b = r >> 9, s = r & 511;
            float2 v = make_float2(d[nt][h * 2] + bias.x, d[nt][h * 2 + 1] + bias.y);
            *(float2*)&g_u[s][b][gb] = v;
        }
    }
}

// =====================================================================
// Kernel 2: mma.sync scan. Changes vs R15:
//  - per-batch-tile barrier (two independent 64-CTA barriers)
//  - q==3 loop-end sync removed (publish directly; sred=buf0, q3 reads buf1)
// =====================================================================
__global__ void __launch_bounds__(NTHR, 1)
timelstm_scan_mma(const float* __restrict__ Wall, const float* __restrict__ Wd,
                  const float* __restrict__ Wdb,  const float* __restrict__ ts,
                  float* __restrict__ out) {
    extern __shared__ char smc[];
    const uint32_t smb = smem_u32(smc);
    float* sred = (float*)(smc + SA);

    const int tid  = threadIdx.x;
    const int lane = tid & 31;
    const int wid  = tid >> 5;
    const int kh   = wid >> 1;
    const int mg   = wid & 1;
    const int jt = blockIdx.x >> 1;
    const int bt = blockIdx.x & 1;
    const int j0 = jt * BJ;
    const int b0 = bt * BB;
    const int gslot = (bt * 4 + (jt >> 4)) * 32;   // per-bt barrier group
    const int rslot = bt * 32;

    for (int idx = tid; idx < 40 * 128; idx += NTHR) {
        int n = idx >> 7;
        int k = (idx & 127) << 2;
        const float* sp = (n < 32)
            ? &Wall[(size_t)((n >> 3) * HDIM + j0 + (n & 7)) * HDIM + k]
            : &Wd[(size_t)(j0 + n - 32) * HDIM + k];
        float4 w = *(const float4*)sp;
        unsigned h0, l0, h1, l1;
        hilo2(w.x, w.y, h0, l0);
        hilo2(w.z, w.w, h1, l1);
        *(uint2*)(smc + SB_H + n * BROW + k * 2) = make_uint2(h0, h1);
        *(uint2*)(smc + SB_L + n * BROW + k * 2) = make_uint2(l0, l1);
    }

    const int tid4 = lane & 3, gid = lane >> 2;
    const int bl_e = tid >> 2;
    const int jp_e = tid & 3;
    const int jc_e = 2 * jp_e;
    const int b_e  = b0 + bl_e;
    const float2 bdv = *(const float2*)&Wdb[j0 + jc_e];
    __syncthreads();

    const uint32_t aoff = ((lane & 7) + ((lane >> 3) & 1) * 8) * AROWB + (lane >> 4) * 16;
    const uint32_t boff = (lane & 7) * BROW + ((lane >> 3) & 1) * 16 + (lane >> 4) * (8 * BROW);
    const uint32_t doff = (lane & 7) * BROW + ((lane >> 3) & 1) * 16;

    const char* gsrc[4];
    gsrc[0] = (const char*)g_hh; gsrc[1] = (const char*)g_hl;
    gsrc[2] = (const char*)g_ch; gsrc[3] = (const char*)g_cl;

    for (int s = 0; s < SEQ; ++s) {
        const int cur = s & 1, nxt = cur ^ 1;
        const size_t curoff = (size_t)cur * BATCH * HDIM * 2;

        // ---- chunk-0 staging FIRST (critical path), then u prefetch ----
#pragma unroll
        for (int t = 0; t < 16; ++t) {
            int idx = tid + t * NTHR;
            int arr = idx >> 10, rem = idx & 1023;
            int row = rem >> 4, seg = rem & 15;
            cpa16(smb + SA + arr * AARR + row * AROWB + seg * 16,
                  gsrc[arr] + curoff + (size_t)(b0 + row) * 1024 + seg * 16);
        }
        CP_COMMIT();

        const float* ub = &g_u[s][b_e][0];
        float2 uF = __ldcg((const float2*)(ub + 0 * HDIM + j0 + jc_e));
        float2 uI = __ldcg((const float2*)(ub + 1 * HDIM + j0 + jc_e));
        float2 uO = __ldcg((const float2*)(ub + 2 * HDIM + j0 + jc_e));
        float2 uC = __ldcg((const float2*)(ub + 3 * HDIM + j0 + jc_e));
        float2 co = __ldcg((const float2*)&g_c[cur][b_e][j0 + jc_e]);
        const float tv = __ldcg(&ts[(size_t)b_e * SEQ + s]);

        float dG[2][4][4] = {};
        float dD[2][4] = {};

#pragma unroll 1
        for (int q = 0; q < 4; ++q) {
            const int buf = q & 1;
            if (q < 3) {
                const int nb = buf ^ 1;
#pragma unroll
                for (int t = 0; t < 16; ++t) {
                    int idx = tid + t * NTHR;
                    int arr = idx >> 10, rem = idx & 1023;
                    int row = rem >> 4, seg = rem & 15;
                    cpa16(smb + SA + nb * ABUF + arr * AARR + row * AROWB + seg * 16,
                          gsrc[arr] + curoff + (size_t)(b0 + row) * 1024 + (q + 1) * 256 + seg * 16);
                }
                CP_COMMIT();
                CP_WAIT(1);
            } else {
                CP_WAIT(0);
            }
            __syncthreads();

            const uint32_t abase = smb + SA + buf * ABUF;
#pragma unroll
            for (int kk = 0; kk < 2; ++kk) {
                const int ksl = kh * 2 + kk;
                const uint32_t kbA = ksl * 32;
                const uint32_t kbB = q * 256 + ksl * 32;

                unsigned gh[8], gl[8], dh[2], dl[2];
                ldsm4(&gh[0], smb + SB_H + 0     + boff + kbB);
                ldsm4(&gh[4], smb + SB_H + 16640 + boff + kbB);
                ldsm4(&gl[0], smb + SB_L + 0     + boff + kbB);
                ldsm4(&gl[4], smb + SB_L + 16640 + boff + kbB);
                ldsm2(dh, smb + SB_H + 33280 + doff + kbB);
                ldsm2(dl, smb + SB_L + 33280 + doff + kbB);

#pragma unroll
                for (int mt = 0; mt < 2; ++mt) {
                    const uint32_t rbase = (uint32_t)(mg * 32 + mt * 16) * AROWB + kbA + aoff;
                    unsigned ah[4], al[4], ch[4], cl[4];
                    ldsm4(ah, abase + 0 * AARR + rbase);
                    ldsm4(al, abase + 1 * AARR + rbase);
                    ldsm4(ch, abase + 2 * AARR + rbase);
                    ldsm4(cl, abase + 3 * AARR + rbase);
#pragma unroll
                    for (int nt = 0; nt < 4; ++nt) {
                        mma16816(dG[mt][nt], ah, &gh[nt * 2]);
                        mma16816(dG[mt][nt], ah, &gl[nt * 2]);
                        mma16816(dG[mt][nt], al, &gh[nt * 2]);
                    }
                    mma16816(dD[mt], ch, dh);
                    mma16816(dD[mt], ch, dl);
                    mma16816(dD[mt], cl, dh);
                }
            }
            if (q < 3) __syncthreads();   // buf reuse guard (not needed after q=3)
        }

        // ---- publish partials (sred = buf0; q=3 read buf1, so no pre-sync) ----
        {
            float* rk = sred + kh * RSETK;
#pragma unroll
            for (int mt = 0; mt < 2; ++mt) {
                const int blr = mg * 32 + mt * 16 + gid;
#pragma unroll
                for (int fr = 0; fr < 4; ++fr) {
                    const int row = blr + (fr >> 1) * 8;
                    const int cp = tid4 * 2 + (fr & 1);
                    float* rr = rk + row * 41;
#pragma unroll
                    for (int nt = 0; nt < 4; ++nt)
                        rr[nt * 8 + cp] = dG[mt][nt][fr];
                    rr[32 + cp] = dD[mt][fr];
                }
            }
        }
        __syncthreads();

        float hn0, hn1;
        {
            float cn[2], hn[2];
            const float uFa[2] = {uF.x, uF.y}, uIa[2] = {uI.x, uI.y};
            const float uOa[2] = {uO.x, uO.y}, uCa[2] = {uC.x, uC.y};
            const float coa[2] = {co.x, co.y}, bda[2] = {bdv.x, bdv.y};
#pragma unroll
            for (int jj = 0; jj < 2; ++jj) {
                const int cb = jc_e + jj;
                float F = 0.f, I_ = 0.f, O_ = 0.f, Ct = 0.f, Dd = 0.f;
#pragma unroll
                for (int k4 = 0; k4 < 4; ++k4) {
                    const float* rr = sred + k4 * RSETK + bl_e * 41;
                    F  += rr[cb];
                    I_ += rr[8 + cb];
                    O_ += rr[16 + cb];
                    Ct += rr[24 + cb];
                    Dd += rr[32 + cb];
                }
                F  += uFa[jj];
                I_ += uIa[jj];
                O_ += uOa[jj];
                Ct += uCa[jj];
                Dd += bda[jj];
                float f   = sigm(F);
                float ii  = sigm(I_);
                float oo  = sigm(O_);
                float ct  = sigm(Ct);
                float cs1 = tanhfast(Dd);
                float cadj = coa[jj] + cs1 * (tv - 1.0f);
                cn[jj] = f * cadj + ii * ct;
                hn[jj] = oo * tanhfast(cn[jj]);
            }
            *(float2*)&g_c[nxt][b_e][j0 + jc_e] = make_float2(cn[0], cn[1]);
            unsigned phh, phl, pch, pcl;
            hilo2(hn[0], hn[1], phh, phl);
            hilo2(cn[0], cn[1], pch, pcl);
            *(unsigned*)&g_hh[nxt][b_e][j0 + jc_e] = phh;
            *(unsigned*)&g_hl[nxt][b_e][j0 + jc_e] = phl;
            *(unsigned*)&g_ch[nxt][b_e][j0 + jc_e] = pch;
            *(unsigned*)&g_cl[nxt][b_e][j0 + jc_e] = pcl;
            hn0 = hn[0]; hn1 = hn[1];
        }

        // ---- per-bt barrier; out[] store overlapped with release wait ----
        __syncthreads();
        unsigned gen = 0;
        if (tid == 0) {
            gen = *(volatile unsigned*)&g_barroot[rslot + 16];
            __threadfence();
            if (atomicAdd(&g_barx[gslot], 1u) == 16u * gen + 15u) {
                if (atomicAdd(&g_barroot[rslot], 1u) == 4u * gen + 3u) {
                    __threadfence();
                    *(volatile unsigned*)&g_barroot[rslot + 16] = gen + 1u;
                }
            }
        }
        *(float2*)&out[((size_t)b_e * SEQ + s) * HDIM + j0 + jc_e] = make_float2(hn0, hn1);
        if (tid == 0) {
            volatile unsigned* vgen = &g_barroot[rslot + 16];
            while (*vgen == gen) { }
            __threadfence();
        }
        __syncthreads();
    }
}

// =====================================================================
extern "C" void kernel_launch(void* const* d_in, const int* in_sizes, int n_in,
                              void* d_out, int out_size) {
    const float* X     = (const float*)d_in[0];
    const float* T     = (const float*)d_in[1];
    const float* Wall  = (const float*)d_in[2];
    const float* Wallb = (const float*)d_in[3];
    const float* Uw    = (const float*)d_in[4];
    const float* Ubb   = (const float*)d_in[5];
    const float* Wd    = (const float*)d_in[6];
    const float* Wdb   = (const float*)d_in[7];
    float* out = (float*)d_out;

    void* p;
    cudaGetSymbolAddress(&p, g_hh); cudaMemsetAsync(p, 0, 2 * BATCH * HDIM * 2, 0);
    cudaGetSymbolAddress(&p, g_hl); cudaMemsetAsync(p, 0, 2 * BATCH * HDIM * 2, 0);
    cudaGetSymbolAddress(&p, g_ch); cudaMemsetAsync(p, 0, 2 * BATCH * HDIM * 2, 0);
    cudaGetSymbolAddress(&p, g_cl); cudaMemsetAsync(p, 0, 2 * BATCH * HDIM * 2, 0);
    cudaGetSymbolAddress(&p, g_c);  cudaMemsetAsync(p, 0, 2 * BATCH * HDIM * 4, 0);
    cudaGetSymbolAddress(&p, g_barx);    cudaMemsetAsync(p, 0, 8 * 32 * 4, 0);
    cudaGetSymbolAddress(&p, g_barroot); cudaMemsetAsync(p, 0, 64 * 4, 0);

    cudaFuncSetAttribute(u_gemm_mma,
                         cudaFuncAttributeMaxDynamicSharedMemorySize, UG_SMEM);
    dim3 ugrid(G4 / 64, (BATCH * SEQ) / 128);
    u_gemm_mma<<<ugrid, 256, UG_SMEM>>>(X, Uw, Ubb, Wallb);

    cudaFuncSetAttribute(timelstm_scan_mma,
                         cudaFuncAttributeMaxDynamicSharedMemorySize, SMEM_SCAN);
    timelstm_scan_mma<<<NBLK, NTHR, SMEM_SCAN>>>(Wall, Wd, Wdb, T, out);
}